// round 9
// baseline (speedup 1.0000x reference)
#include <cuda_runtime.h>
#include <cstdint>

#define NN  100000
#define EIN 1600000
#define ECN 800000
#define GN  2000
#define FDIM 512
#define CC  128

// -------- scratch (device globals; no allocation) --------
__device__ float g_xw[NN*CC];
__device__ float g_f[NN*CC];
__device__ float g_z[NN*CC];
__device__ float g_el[NN*4];
__device__ float g_er[NN*4];
__device__ float g_alpha[ECN*4];
__device__ float g_iso[NN];
__device__ float g_isi[NN];
__device__ float g_att[NN];
__device__ float g_gsum[GN*CC];
__device__ float g_gcnt[GN];
__device__ float g_bnsum[CC];
__device__ float g_bnsq[CC];
__device__ float g_bnscale[CC];
__device__ float g_bnshift[CC];
__device__ float g_wp[FDIM*256];
__device__ float g_cvec[256];
// CSR scratch
__device__ int g_idegi[NN];
__device__ int g_idegc[NN];
__device__ int g_rpi[NN];
__device__ int g_rpc[NN];
__device__ int g_curi[NN];
__device__ int g_curc[NN];
__device__ int g_bsum[1024];
__device__ int g_ci[EIN];
__device__ int g_ccol[ECN];

__device__ __forceinline__ float leakyr(float x) { return x >= 0.f ? x : 0.2f * x; }

__device__ __forceinline__ float to_tf32(float x) {
    float r;
    asm("cvt.rna.tf32.f32 %0, %1;" : "=f"(r) : "f"(x));
    return r;
}

__device__ __forceinline__ void mma_tf32(float* d, const uint32_t* a, const uint32_t* b) {
    asm volatile(
        "mma.sync.aligned.m16n8k8.row.col.f32.tf32.tf32.f32 "
        "{%0,%1,%2,%3}, {%4,%5,%6,%7}, {%8,%9}, {%0,%1,%2,%3};"
        : "+f"(d[0]), "+f"(d[1]), "+f"(d[2]), "+f"(d[3])
        : "r"(a[0]), "r"(a[1]), "r"(a[2]), "r"(a[3]), "r"(b[0]), "r"(b[1]));
}

__device__ __forceinline__ void cp16(uint32_t dst, const void* src, int sz) {
    asm volatile("cp.async.cg.shared.global [%0], [%1], 16, %2;"
                 :: "r"(dst), "l"(src), "r"(sz) : "memory");
}

// -------- utility --------
__global__ void fill_kernel(float* p, float v, int n) {
    int i = blockIdx.x * blockDim.x + threadIdx.x;
    if (i < n) p[i] = v;
}
__global__ void zero_layer(float* el, float* er, float* bnsum, float* bnsq) {
    int i = blockIdx.x * blockDim.x + threadIdx.x;
    if (i < NN * 4) { el[i] = 0.f; er[i] = 0.f; }
    if (i < CC) { bnsum[i] = 0.f; bnsq[i] = 0.f; }
}
__global__ void init_zero(float* iso, int* idegi, int* idegc, float* att) {
    int i = blockIdx.x * blockDim.x + threadIdx.x;
    if (i < NN) { iso[i] = 0.f; idegi[i] = 0; idegc[i] = 0; att[i] = 0.f; }
}
__global__ void edge_deg(const int* __restrict__ isrc, const int* __restrict__ idst,
                         const int* __restrict__ cdst, float* iso, int* idegi, int* idegc) {
    int t = blockIdx.x * blockDim.x + threadIdx.x;
    if (t < EIN) {
        atomicAdd(&iso[isrc[t]], 1.f);
        atomicAdd(&idegi[idst[t]], 1);
    } else if (t < EIN + ECN) {
        atomicAdd(&idegc[cdst[t - EIN]], 1);
    }
}
__global__ void inv_both(float* iso, const int* __restrict__ idegi, float* isi) {
    int i = blockIdx.x * blockDim.x + threadIdx.x;
    if (i >= NN) return;
    iso[i] = rsqrtf(fmaxf(iso[i], 1.f));
    isi[i] = rsqrtf(fmaxf((float)idegi[i], 1.f));
}

// -------- dual 3-stage exclusive scan --------
__global__ void scan1dual(const int* __restrict__ in1, const int* __restrict__ in2,
                          int* out1, int* out2, int* bsum, int n) {
    __shared__ int sh1[256], sh2[256];
    int i = blockIdx.x * 256 + threadIdx.x;
    int v1 = (i < n) ? in1[i] : 0;
    int v2 = (i < n) ? in2[i] : 0;
    sh1[threadIdx.x] = v1; sh2[threadIdx.x] = v2;
    __syncthreads();
    for (int off = 1; off < 256; off <<= 1) {
        int t1 = (threadIdx.x >= off) ? sh1[threadIdx.x - off] : 0;
        int t2 = (threadIdx.x >= off) ? sh2[threadIdx.x - off] : 0;
        __syncthreads();
        sh1[threadIdx.x] += t1; sh2[threadIdx.x] += t2;
        __syncthreads();
    }
    if (i < n) { out1[i] = sh1[threadIdx.x] - v1; out2[i] = sh2[threadIdx.x] - v2; }
    if (threadIdx.x == 255) {
        bsum[blockIdx.x] = sh1[255];
        bsum[512 + blockIdx.x] = sh2[255];
    }
}
__global__ void scan2dual(int* bsum, int nb) {
    __shared__ int sh[512];
    int t = threadIdx.x;
    for (int a = 0; a < 2; a++) {
        int* bs = bsum + a * 512;
        int v = (t < nb) ? bs[t] : 0;
        sh[t] = v;
        __syncthreads();
        for (int off = 1; off < 512; off <<= 1) {
            int x = (t >= off) ? sh[t - off] : 0;
            __syncthreads();
            sh[t] += x;
            __syncthreads();
        }
        if (t < nb) bs[t] = sh[t] - v;
        __syncthreads();
    }
}
__global__ void scan3dual(int* out1, int* out2, const int* __restrict__ bsum,
                          int* cur1, int* cur2, int n) {
    int i = blockIdx.x * 256 + threadIdx.x;
    if (i >= n) return;
    int r1 = out1[i] + bsum[blockIdx.x];
    int r2 = out2[i] + bsum[512 + blockIdx.x];
    out1[i] = r1; out2[i] = r2;
    cur1[i] = r1; cur2[i] = r2;
}
__global__ void scatter_dual(const int* __restrict__ isrc, const int* __restrict__ idst,
                             const int* __restrict__ csrc, const int* __restrict__ cdst,
                             int* curi, int* curc, int* ci, int* ccol) {
    int t = blockIdx.x * blockDim.x + threadIdx.x;
    if (t < EIN) {
        int p = atomicAdd(&curi[idst[t]], 1);
        ci[p] = isrc[t];
    } else if (t < EIN + ECN) {
        int e = t - EIN;
        int p = atomicAdd(&curc[cdst[e]], 1);
        ccol[p] = csrc[e];
    }
}

// -------- weight prep --------
__global__ void prep_w(const float* __restrict__ Wgc, const float* __restrict__ Wgat,
                       const float* __restrict__ s, int K, float* __restrict__ Wp)
{
    int i = blockIdx.x * 256 + threadIdx.x;
    if (i >= K * 256) return;
    int k = i >> 8, j = i & 255;
    float sv = s ? s[k] : 1.f;
    float w = (j < 128) ? Wgc[k * 128 + j] : Wgat[k * 128 + j - 128];
    Wp[i] = to_tf32(sv * w);
}
__global__ __launch_bounds__(128) void prep_c(
    const float* __restrict__ Wgc, const float* __restrict__ Wgat,
    const float* __restrict__ b, int K, float* __restrict__ cvec)
{
    __shared__ float sh[128];
    int j = blockIdx.x;
    int t = threadIdx.x;
    float acc = 0.f;
    if (b) {
        const float* W = (j < 128) ? (Wgc + j) : (Wgat + j - 128);
        for (int k = t; k < K; k += 128)
            acc += b[k] * W[(size_t)k * 128];
    }
    sh[t] = acc;
    __syncthreads();
    for (int off = 64; off; off >>= 1) {
        if (t < off) sh[t] += sh[t + off];
        __syncthreads();
    }
    if (t == 0) cvec[j] = sh[0];
}

// ===================================================================
// Dual-GEMM + fused attention dot products (el/er) in epilogue
// ===================================================================
__global__ __launch_bounds__(512, 1) void gemm_dual_async(
    const float* __restrict__ A, const float* __restrict__ Wp,
    const float* __restrict__ cvec,
    float* __restrict__ Ca, float* __restrict__ Cb,
    const float* __restrict__ rowscale,
    const float* __restrict__ alv, const float* __restrict__ arv,
    float* __restrict__ el, float* __restrict__ er,
    int M, int K, int H)
{
    __shared__ float As[3][128 * 16];
    __shared__ float Bs[3][16 * 256];

    const int tid = threadIdx.x;
    const int lane = tid & 31;
    const int wid = tid >> 5;
    const int wm = wid & 3;
    const int wn = wid >> 2;
    const int row0 = blockIdx.x * 128;
    const int iters = K >> 4;

    float acc[2][8][4];
#pragma unroll
    for (int i = 0; i < 2; i++)
#pragma unroll
        for (int j = 0; j < 8; j++)
#pragma unroll
            for (int q = 0; q < 4; q++) acc[i][j][q] = 0.f;

    const int ar_ = tid >> 2, akg = tid & 3;
    const int a_soff = ar_ * 16 + ((akg * 4) ^ (4 * (ar_ & 3)));
    const int a_sz = (row0 + ar_ < M) ? 16 : 0;
    const float* a_src_base = A + (size_t)(row0 + ar_) * K + akg * 4;

    auto loadTile = [&](int it) {
        int buf = it % 3;
        int k0 = it * 16;
        cp16((uint32_t)__cvta_generic_to_shared(&As[buf][a_soff]), a_src_base + k0, a_sz);
#pragma unroll
        for (int i = 0; i < 2; i++) {
            int l = i * 512 + tid;
            int k = l >> 6, n4 = (l & 63) * 4;
            uint32_t dst = (uint32_t)__cvta_generic_to_shared(
                &Bs[buf][k * 256 + (n4 ^ (8 * (k & 3)))]);
            cp16(dst, Wp + (size_t)(k0 + k) * 256 + n4, 16);
        }
        asm volatile("cp.async.commit_group;" ::: "memory");
    };

    loadTile(0);
    if (iters > 1) loadTile(1);
    else asm volatile("cp.async.commit_group;" ::: "memory");

    for (int it = 0; it < iters; ++it) {
        asm volatile("cp.async.wait_group 1;" ::: "memory");
        __syncthreads();
        if (it + 2 < iters) loadTile(it + 2);
        else asm volatile("cp.async.commit_group;" ::: "memory");

        const float* as = As[it % 3];
        const float* bs = Bs[it % 3];

#pragma unroll
        for (int kk = 0; kk < 2; kk++) {
            int k8 = kk * 8;
            uint32_t afr[2][4], bfr[8][2];
#pragma unroll
            for (int i = 0; i < 2; i++) {
                int r = wm * 32 + i * 16 + (lane >> 2);
                int c = k8 + (lane & 3);
                int sw = 4 * (r & 3);
                int r2 = r + 8;
                int sw2 = 4 * (r2 & 3);
                afr[i][0] = __float_as_uint(to_tf32(as[r * 16 + (c ^ sw)]));
                afr[i][1] = __float_as_uint(to_tf32(as[r2 * 16 + (c ^ sw2)]));
                afr[i][2] = __float_as_uint(to_tf32(as[r * 16 + ((c + 4) ^ sw)]));
                afr[i][3] = __float_as_uint(to_tf32(as[r2 * 16 + ((c + 4) ^ sw2)]));
            }
#pragma unroll
            for (int j = 0; j < 8; j++) {
                int n = wn * 64 + j * 8 + (lane >> 2);
                int k = k8 + (lane & 3);
                int k2 = k + 4;
                bfr[j][0] = __float_as_uint(bs[k * 256 + (n ^ (8 * (k & 3)))]);
                bfr[j][1] = __float_as_uint(bs[k2 * 256 + (n ^ (8 * (k2 & 3)))]);
            }
#pragma unroll
            for (int i = 0; i < 2; i++)
#pragma unroll
                for (int j = 0; j < 8; j++)
                    mma_tf32(acc[i][j], afr[i], bfr[j]);
        }
    }

    // ---- store epilogue ----
#pragma unroll
    for (int i = 0; i < 2; i++) {
        int r = row0 + wm * 32 + i * 16 + (lane >> 2);
#pragma unroll
        for (int j = 0; j < 8; j++) {
            int col = wn * 64 + j * 8 + (lane & 3) * 2;
            float c0 = __ldg(cvec + col), c1 = __ldg(cvec + col + 1);
            float* dstm;
            int c;
            bool isA = (col < 128);
            if (isA) { dstm = Ca; c = col; }
            else     { dstm = Cb; c = col - 128; }
            if (r < M) {
                float s = isA ? __ldg(rowscale + r) : 1.f;
                *(float2*)(dstm + (size_t)r * 128 + c) =
                    make_float2((acc[i][j][0] + c0) * s, (acc[i][j][1] + c1) * s);
            }
            if (r + 8 < M) {
                float s = isA ? __ldg(rowscale + r + 8) : 1.f;
                *(float2*)(dstm + (size_t)(r + 8) * 128 + c) =
                    make_float2((acc[i][j][2] + c0) * s, (acc[i][j][3] + c1) * s);
            }
        }
    }

    // ---- fused el/er: warps holding f columns (wn >= 2) ----
    if (wn >= 2) {
        const int hmask = (H == 4) ? 1 : 0;
        float pel[4][2], per_[4][2];
#pragma unroll
        for (int rr = 0; rr < 4; rr++) { pel[rr][0] = pel[rr][1] = 0.f; per_[rr][0] = per_[rr][1] = 0.f; }
#pragma unroll
        for (int i = 0; i < 2; i++)
#pragma unroll
            for (int j = 0; j < 8; j++) {
                int col = wn * 64 + j * 8 + (lane & 3) * 2;
                int cf = col - 128;
                float a0 = __ldg(alv + cf), a1 = __ldg(alv + cf + 1);
                float b0 = __ldg(arv + cf), b1 = __ldg(arv + cf + 1);
                float c0 = __ldg(cvec + col), c1 = __ldg(cvec + col + 1);
                int hg = (j >> 2) & hmask;
                float f0 = acc[i][j][0] + c0, f1 = acc[i][j][1] + c1;
                float f2 = acc[i][j][2] + c0, f3 = acc[i][j][3] + c1;
                pel[i * 2 + 0][hg] += f0 * a0 + f1 * a1;
                per_[i * 2 + 0][hg] += f0 * b0 + f1 * b1;
                pel[i * 2 + 1][hg] += f2 * a0 + f3 * a1;
                per_[i * 2 + 1][hg] += f2 * b0 + f3 * b1;
            }
#pragma unroll
        for (int rr = 0; rr < 4; rr++)
#pragma unroll
            for (int hg = 0; hg < 2; hg++) {
                float v = pel[rr][hg];
                v += __shfl_xor_sync(0xffffffffu, v, 1);
                v += __shfl_xor_sync(0xffffffffu, v, 2);
                pel[rr][hg] = v;
                float w = per_[rr][hg];
                w += __shfl_xor_sync(0xffffffffu, w, 1);
                w += __shfl_xor_sync(0xffffffffu, w, 2);
                per_[rr][hg] = w;
            }
        if ((lane & 3) == 0) {
#pragma unroll
            for (int rr = 0; rr < 4; rr++) {
                int row = row0 + wm * 32 + (rr >> 1) * 16 + (lane >> 2) + (rr & 1) * 8;
                if (row < M) {
#pragma unroll
                    for (int hg = 0; hg < 2; hg++) {
                        if (hg > hmask) break;
                        int h = (H == 4) ? ((wn - 2) * 2 + hg) : 0;
                        atomicAdd(&el[(size_t)row * H + h], pel[rr][hg]);
                        atomicAdd(&er[(size_t)row * H + h], per_[rr][hg]);
                    }
                }
            }
        }
    }
}

// -------- per-node softmax: warp-per-node grid-stride, alpha in CSR order --------
template<int H>
__global__ __launch_bounds__(128) void gat_ms_alpha(
    const float* __restrict__ el, const float* __restrict__ er,
    const int* __restrict__ rpc, const int* __restrict__ degc,
    const int* __restrict__ ccol, float* __restrict__ alpha, float* att)
{
    const int lane = threadIdx.x & 31;
    const int warp = (blockIdx.x * blockDim.x + threadIdx.x) >> 5;
    const int nwarps = (gridDim.x * blockDim.x) >> 5;
    const float4* el4 = (const float4*)el;
    const float4* er4 = (const float4*)er;

    for (int n = warp; n < NN; n += nwarps) {
        int c0 = __ldg(rpc + n), deg = __ldg(degc + n);
        if (deg == 0) continue;
        int cend = c0 + deg;

        if (H == 4) {
            float4 ern = __ldg(er4 + n);
            float m0 = -1e30f, m1 = -1e30f, m2 = -1e30f, m3 = -1e30f;
            float s0 = 0.f, s1 = 0.f, s2 = 0.f, s3 = 0.f;
            for (int j = c0 + lane; j < cend; j += 32) {
                int sn = __ldg(ccol + j);
                float4 e4 = __ldg(el4 + sn);
                float e0 = leakyr(e4.x + ern.x), e1 = leakyr(e4.y + ern.y);
                float e2 = leakyr(e4.z + ern.z), e3 = leakyr(e4.w + ern.w);
                if (e0 > m0) { s0 *= __expf(m0 - e0); m0 = e0; } s0 += __expf(e0 - m0);
                if (e1 > m1) { s1 *= __expf(m1 - e1); m1 = e1; } s1 += __expf(e1 - m1);
                if (e2 > m2) { s2 *= __expf(m2 - e2); m2 = e2; } s2 += __expf(e2 - m2);
                if (e3 > m3) { s3 *= __expf(m3 - e3); m3 = e3; } s3 += __expf(e3 - m3);
            }
#pragma unroll
            for (int off = 16; off; off >>= 1) {
                float mo, so, mm;
                mo = __shfl_xor_sync(0xffffffffu, m0, off); so = __shfl_xor_sync(0xffffffffu, s0, off);
                mm = fmaxf(m0, mo); s0 = s0 * __expf(m0 - mm) + so * __expf(mo - mm); m0 = mm;
                mo = __shfl_xor_sync(0xffffffffu, m1, off); so = __shfl_xor_sync(0xffffffffu, s1, off);
                mm = fmaxf(m1, mo); s1 = s1 * __expf(m1 - mm) + so * __expf(mo - mm); m1 = mm;
                mo = __shfl_xor_sync(0xffffffffu, m2, off); so = __shfl_xor_sync(0xffffffffu, s2, off);
                mm = fmaxf(m2, mo); s2 = s2 * __expf(m2 - mm) + so * __expf(mo - mm); m2 = mm;
                mo = __shfl_xor_sync(0xffffffffu, m3, off); so = __shfl_xor_sync(0xffffffffu, s3, off);
                mm = fmaxf(m3, mo); s3 = s3 * __expf(m3 - mm) + so * __expf(mo - mm); m3 = mm;
            }
            float i0 = 1.f / s0, i1 = 1.f / s1, i2 = 1.f / s2, i3 = 1.f / s3;
            for (int j = c0 + lane; j < cend; j += 32) {
                int sn = __ldg(ccol + j);
                float4 e4 = __ldg(el4 + sn);
                float4 o;
                o.x = __expf(leakyr(e4.x + ern.x) - m0) * i0;
                o.y = __expf(leakyr(e4.y + ern.y) - m1) * i1;
                o.z = __expf(leakyr(e4.z + ern.z) - m2) * i2;
                o.w = __expf(leakyr(e4.w + ern.w) - m3) * i3;
                ((float4*)alpha)[j] = o;
            }
        } else {
            float ern = __ldg(er + n);
            float m = -1e30f, s = 0.f;
            for (int j = c0 + lane; j < cend; j += 32) {
                int sn = __ldg(ccol + j);
                float e = leakyr(__ldg(el + sn) + ern);
                if (e > m) { s *= __expf(m - e); m = e; }
                s += __expf(e - m);
            }
#pragma unroll
            for (int off = 16; off; off >>= 1) {
                float mo = __shfl_xor_sync(0xffffffffu, m, off);
                float so = __shfl_xor_sync(0xffffffffu, s, off);
                float mm = fmaxf(m, mo);
                s = s * __expf(m - mm) + so * __expf(mo - mm);
                m = mm;
            }
            float inv = 1.f / s;
            for (int j = c0 + lane; j < cend; j += 32) {
                int sn = __ldg(ccol + j);
                float e = leakyr(__ldg(el + sn) + ern);
                float a = __expf(e - m) * inv;
                alpha[j] = a;
                atomicAdd(&att[sn], a);
            }
        }
    }
}

// ===================================================================
// Fused layer: block-per-node (2048 blocks preserved), 64 threads,
// float2 per thread — halves LSU issue vs 128-thread scalar version.
// ===================================================================
template<int H, int DO_LEAKY>
__global__ __launch_bounds__(64) void layer_fused(
    const float* __restrict__ xw, const float* __restrict__ f,
    const float* __restrict__ alpha, const float* __restrict__ isi,
    const int* __restrict__ rpi, const int* __restrict__ degi, const int* __restrict__ ci,
    const int* __restrict__ rpc, const int* __restrict__ degc, const int* __restrict__ ccol,
    const float* __restrict__ bgc, const float* __restrict__ bga,
    float* __restrict__ z, float* __restrict__ bnsum, float* __restrict__ bnsq)
{
    const int t = threadIdx.x;                 // 0..63; channels 2t, 2t+1
    const int h = (H == 1) ? 0 : (t >> 4);     // 2t>>5 == t>>4
    const float2* xw2 = (const float2*)xw;     // row stride 64
    const float2* f2 = (const float2*)f;
    float2 bc;
    {
        float2 b1 = ((const float2*)bgc)[t];
        float2 b2 = ((const float2*)bga)[t];
        bc.x = b1.x + b2.x; bc.y = b1.y + b2.y;
    }
    float2 ls = make_float2(0.f, 0.f), lq = make_float2(0.f, 0.f);

    for (int n = blockIdx.x; n < NN; n += gridDim.x) {
        // GraphConv gather
        float2 a = make_float2(0.f, 0.f);
        int j = __ldg(rpi + n);
        int bend = j + __ldg(degi + n);
        for (; j + 4 <= bend; j += 4) {
            int s0 = __ldg(ci + j), s1 = __ldg(ci + j + 1);
            int s2 = __ldg(ci + j + 2), s3 = __ldg(ci + j + 3);
            float2 v0 = __ldg(xw2 + (size_t)s0 * 64 + t);
            float2 v1 = __ldg(xw2 + (size_t)s1 * 64 + t);
            float2 v2 = __ldg(xw2 + (size_t)s2 * 64 + t);
            float2 v3 = __ldg(xw2 + (size_t)s3 * 64 + t);
            a.x += (v0.x + v1.x) + (v2.x + v3.x);
            a.y += (v0.y + v1.y) + (v2.y + v3.y);
        }
        for (; j < bend; j++) {
            float2 v = __ldg(xw2 + (size_t)__ldg(ci + j) * 64 + t);
            a.x += v.x; a.y += v.y;
        }

        // GAT gather with CSR-ordered alpha
        float2 g = make_float2(0.f, 0.f);
        int k = __ldg(rpc + n);
        int cend = k + __ldg(degc + n);
        for (; k + 4 <= cend; k += 4) {
            int s0 = __ldg(ccol + k), s1 = __ldg(ccol + k + 1);
            int s2 = __ldg(ccol + k + 2), s3 = __ldg(ccol + k + 3);
            float a0 = __ldg(alpha + (size_t)(k + 0) * H + h);
            float a1 = __ldg(alpha + (size_t)(k + 1) * H + h);
            float a2 = __ldg(alpha + (size_t)(k + 2) * H + h);
            float a3 = __ldg(alpha + (size_t)(k + 3) * H + h);
            float2 v0 = __ldg(f2 + (size_t)s0 * 64 + t);
            float2 v1 = __ldg(f2 + (size_t)s1 * 64 + t);
            float2 v2 = __ldg(f2 + (size_t)s2 * 64 + t);
            float2 v3 = __ldg(f2 + (size_t)s3 * 64 + t);
            g.x += a0 * v0.x + a1 * v1.x + a2 * v2.x + a3 * v3.x;
            g.y += a0 * v0.y + a1 * v1.y + a2 * v2.y + a3 * v3.y;
        }
        for (; k < cend; k++) {
            int s0 = __ldg(ccol + k);
            float a0 = __ldg(alpha + (size_t)k * H + h);
            float2 v = __ldg(f2 + (size_t)s0 * 64 + t);
            g.x += a0 * v.x; g.y += a0 * v.y;
        }

        float is = __ldg(isi + n);
        float2 v;
        v.x = a.x * is + g.x + bc.x;
        v.y = a.y * is + g.y + bc.y;
        if (DO_LEAKY) { v.x = leakyr(v.x); v.y = leakyr(v.y); }
        ((float2*)z)[(size_t)n * 64 + t] = v;
        ls.x += v.x; ls.y += v.y;
        lq.x += v.x * v.x; lq.y += v.y * v.y;
    }
    atomicAdd(&bnsum[2 * t + 0], ls.x);
    atomicAdd(&bnsum[2 * t + 1], ls.y);
    atomicAdd(&bnsq[2 * t + 0], lq.x);
    atomicAdd(&bnsq[2 * t + 1], lq.y);
}

__global__ void bn_prep(const float* bnsum, const float* bnsq, const float* __restrict__ g,
                        const float* __restrict__ be, float* scale, float* shift)
{
    int c = threadIdx.x;
    if (c >= CC) return;
    float mu = bnsum[c] / (float)NN;
    float var = bnsq[c] / (float)NN - mu * mu;
    float sc = g[c] * rsqrtf(var + 1e-5f);
    scale[c] = sc;
    shift[c] = be[c] - mu * sc;
}

// -------- pooling (layer-3 BN affine fused) --------
__global__ void pool_kernel(const float* __restrict__ z, const float* __restrict__ scale,
                            const float* __restrict__ shift, const float* __restrict__ att,
                            const int* __restrict__ gid, float* gsum)
{
    int idx = blockIdx.x * blockDim.x + threadIdx.x;
    if (idx >= NN * 128) return;
    int n = idx >> 7, ch = idx & 127;
    float v = z[idx] * scale[ch] + shift[ch];
    atomicAdd(&gsum[gid[n] * 128 + ch], v * att[n]);
}
__global__ void gcnt_kernel(const int* __restrict__ gid, float* gcnt) {
    int n = blockIdx.x * blockDim.x + threadIdx.x;
    if (n < NN) atomicAdd(&gcnt[gid[n]], 1.f);
}
__global__ void out_kernel(const float* __restrict__ gsum, const float* __restrict__ gcnt,
                           const float* __restrict__ att, float* __restrict__ out)
{
    int i = blockIdx.x * blockDim.x + threadIdx.x;
    if (i < GN * 128) {
        out[i] = gsum[i] / fmaxf(gcnt[i >> 7], 1.f);
    } else if (i < GN * 128 + NN) {
        out[i] = att[i - GN * 128];
    }
}

static inline int cdiv(int a, int b) { return (a + b - 1) / b; }

extern "C" void kernel_launch(void* const* d_in, const int* in_sizes, int n_in,
                              void* d_out, int out_size)
{
    (void)in_sizes; (void)n_in; (void)out_size;
    const float* feat = (const float*)d_in[0];
    const int* isrc = (const int*)d_in[1];
    const int* idst = (const int*)d_in[2];
    const int* csrc = (const int*)d_in[3];
    const int* cdst = (const int*)d_in[4];
    const int* gid  = (const int*)d_in[5];
    const float* Wgc[3]  = {(const float*)d_in[6],  (const float*)d_in[12], (const float*)d_in[18]};
    const float* bgc[3]  = {(const float*)d_in[7],  (const float*)d_in[13], (const float*)d_in[19]};
    const float* Wgat[3] = {(const float*)d_in[8],  (const float*)d_in[14], (const float*)d_in[20]};
    const float* al[3]   = {(const float*)d_in[9],  (const float*)d_in[15], (const float*)d_in[21]};
    const float* ar[3]   = {(const float*)d_in[10], (const float*)d_in[16], (const float*)d_in[22]};
    const float* bga[3]  = {(const float*)d_in[11], (const float*)d_in[17], (const float*)d_in[23]};
    const float* gam[3]  = {(const float*)d_in[24], (const float*)d_in[26], (const float*)d_in[28]};
    const float* bet[3]  = {(const float*)d_in[25], (const float*)d_in[27], (const float*)d_in[29]};
    float* out = (float*)d_out;

    float *xw, *f, *z, *el, *er, *alpha, *wp, *cvec;
    float *iso, *isi, *att, *gsum, *gcnt, *bnsum, *bnsq, *bnscale, *bnshift;
    int *idegi, *idegc, *rpi, *rpc, *curi, *curc, *bsum, *ci, *ccol;
    cudaGetSymbolAddress((void**)&xw, g_xw);
    cudaGetSymbolAddress((void**)&f, g_f);
    cudaGetSymbolAddress((void**)&z, g_z);
    cudaGetSymbolAddress((void**)&el, g_el);
    cudaGetSymbolAddress((void**)&er, g_er);
    cudaGetSymbolAddress((void**)&alpha, g_alpha);
    cudaGetSymbolAddress((void**)&wp, g_wp);
    cudaGetSymbolAddress((void**)&cvec, g_cvec);
    cudaGetSymbolAddress((void**)&iso, g_iso);
    cudaGetSymbolAddress((void**)&isi, g_isi);
    cudaGetSymbolAddress((void**)&att, g_att);
    cudaGetSymbolAddress((void**)&gsum, g_gsum);
    cudaGetSymbolAddress((void**)&gcnt, g_gcnt);
    cudaGetSymbolAddress((void**)&bnsum, g_bnsum);
    cudaGetSymbolAddress((void**)&bnsq, g_bnsq);
    cudaGetSymbolAddress((void**)&bnscale, g_bnscale);
    cudaGetSymbolAddress((void**)&bnshift, g_bnshift);
    cudaGetSymbolAddress((void**)&idegi, g_idegi);
    cudaGetSymbolAddress((void**)&idegc, g_idegc);
    cudaGetSymbolAddress((void**)&rpi, g_rpi);
    cudaGetSymbolAddress((void**)&rpc, g_rpc);
    cudaGetSymbolAddress((void**)&curi, g_curi);
    cudaGetSymbolAddress((void**)&curc, g_curc);
    cudaGetSymbolAddress((void**)&bsum, g_bsum);
    cudaGetSymbolAddress((void**)&ci, g_ci);
    cudaGetSymbolAddress((void**)&ccol, g_ccol);

    const int NB = cdiv(NN, 256);

    prep_w<<<cdiv(FDIM * 256, 256), 256>>>(Wgc[0], Wgat[0], nullptr, FDIM, wp);
    prep_c<<<256, 128>>>(Wgc[0], Wgat[0], nullptr, FDIM, cvec);
    init_zero<<<cdiv(NN, 256), 256>>>(iso, idegi, idegc, att);
    edge_deg<<<cdiv(EIN + ECN, 256), 256>>>(isrc, idst, cdst, iso, idegi, idegc);
    inv_both<<<cdiv(NN, 256), 256>>>(iso, idegi, isi);

    // CSR build (dual)
    scan1dual<<<NB, 256>>>(idegi, idegc, rpi, rpc, bsum, NN);
    scan2dual<<<1, 512>>>(bsum, NB);
    scan3dual<<<NB, 256>>>(rpi, rpc, bsum, curi, curc, NN);
    scatter_dual<<<cdiv(EIN + ECN, 256), 256>>>(isrc, idst, csrc, cdst, curi, curc, ci, ccol);

    const int Hs[3] = {4, 4, 1};
    for (int L = 0; L < 3; L++) {
        int K = (L == 0) ? FDIM : CC;
        int H = Hs[L];

        if (L > 0) {
            prep_w<<<cdiv(K * 256, 256), 256>>>(Wgc[L], Wgat[L], bnscale, K, wp);
            prep_c<<<256, 128>>>(Wgc[L], Wgat[L], bnshift, K, cvec);
        }
        zero_layer<<<cdiv(NN * 4, 256), 256>>>(el, er, bnsum, bnsq);
        gemm_dual_async<<<cdiv(NN, 128), 512>>>((L == 0) ? feat : z, wp, cvec, xw, f,
                                                iso, al[L], ar[L], el, er, NN, K, H);

        if (H == 4)
            gat_ms_alpha<4><<<2048, 128>>>(el, er, rpc, idegc, ccol, alpha, nullptr);
        else
            gat_ms_alpha<1><<<2048, 128>>>(el, er, rpc, idegc, ccol, alpha, att);

        if (L < 2)
            layer_fused<4, 1><<<2048, 64>>>(xw, f, alpha, isi, rpi, idegi, ci,
                                            rpc, idegc, ccol, bgc[L], bga[L],
                                            z, bnsum, bnsq);
        else
            layer_fused<1, 0><<<2048, 64>>>(xw, f, alpha, isi, rpi, idegi, ci,
                                            rpc, idegc, ccol, bgc[L], bga[L],
                                            z, bnsum, bnsq);

        bn_prep<<<1, 128>>>(bnsum, bnsq, gam[L], bet[L], bnscale, bnshift);
    }

    // ---- pooling (bn affine fused) ----
    fill_kernel<<<cdiv(GN * CC, 256), 256>>>(gsum, 0.f, GN * CC);
    fill_kernel<<<cdiv(GN, 256), 256>>>(gcnt, 0.f, GN);
    gcnt_kernel<<<cdiv(NN, 256), 256>>>(gid, gcnt);
    pool_kernel<<<cdiv(NN * CC, 256), 256>>>(z, bnscale, bnshift, att, gid, gsum);
    out_kernel<<<cdiv(GN * CC + NN, 256), 256>>>(gsum, gcnt, att, out);
}

// round 12
// speedup vs baseline: 1.2535x; 1.2535x over previous
#include <cuda_runtime.h>
#include <cuda_fp16.h>
#include <cstdint>

#define NN  100000
#define EIN 1600000
#define ECN 800000
#define GN  2000
#define FDIM 512
#define CC  128

// -------- scratch (device globals; no allocation) --------
__device__ __half g_xw[NN*CC];
__device__ __half g_f[NN*CC];
__device__ float g_z[NN*CC];
__device__ float g_el[NN*4];
__device__ float g_er[NN*4];
__device__ float g_alpha[ECN*4];
__device__ float g_iso[NN];
__device__ float g_isi[NN];
__device__ float g_att[NN];
__device__ float g_gsum[GN*CC];
__device__ float g_gcnt[GN];
__device__ float g_bnsum[CC];
__device__ float g_bnsq[CC];
__device__ float g_bnscale[CC];
__device__ float g_bnshift[CC];
__device__ float g_wp[FDIM*256];
__device__ float g_cvec[256];
// CSR scratch
__device__ int g_idegi[NN];
__device__ int g_idegc[NN];
__device__ int g_rpi[NN];
__device__ int g_rpc[NN];
__device__ int g_curi[NN];
__device__ int g_curc[NN];
__device__ int g_bsum[1024];
__device__ int g_ci[EIN];
__device__ int g_ccol[ECN];

__device__ __forceinline__ float leakyr(float x) { return x >= 0.f ? x : 0.2f * x; }

__device__ __forceinline__ float to_tf32(float x) {
    float r;
    asm("cvt.rna.tf32.f32 %0, %1;" : "=f"(r) : "f"(x));
    return r;
}

__device__ __forceinline__ void mma_tf32(float* d, const uint32_t* a, const uint32_t* b) {
    asm volatile(
        "mma.sync.aligned.m16n8k8.row.col.f32.tf32.tf32.f32 "
        "{%0,%1,%2,%3}, {%4,%5,%6,%7}, {%8,%9}, {%0,%1,%2,%3};"
        : "+f"(d[0]), "+f"(d[1]), "+f"(d[2]), "+f"(d[3])
        : "r"(a[0]), "r"(a[1]), "r"(a[2]), "r"(a[3]), "r"(b[0]), "r"(b[1]));
}

__device__ __forceinline__ void cp16(uint32_t dst, const void* src, int sz) {
    asm volatile("cp.async.cg.shared.global [%0], [%1], 16, %2;"
                 :: "r"(dst), "l"(src), "r"(sz) : "memory");
}

// -------- utility --------
__global__ void fill_kernel(float* p, float v, int n) {
    int i = blockIdx.x * blockDim.x + threadIdx.x;
    if (i < n) p[i] = v;
}
__global__ void zero_layer(float* el, float* er, float* bnsum, float* bnsq) {
    int i = blockIdx.x * blockDim.x + threadIdx.x;
    if (i < NN * 4) { el[i] = 0.f; er[i] = 0.f; }
    if (i < CC) { bnsum[i] = 0.f; bnsq[i] = 0.f; }
}
__global__ void init_zero(float* iso, int* idegi, int* idegc, float* att) {
    int i = blockIdx.x * blockDim.x + threadIdx.x;
    if (i < NN) { iso[i] = 0.f; idegi[i] = 0; idegc[i] = 0; att[i] = 0.f; }
}
__global__ void edge_deg(const int* __restrict__ isrc, const int* __restrict__ idst,
                         const int* __restrict__ cdst, float* iso, int* idegi, int* idegc) {
    int t = blockIdx.x * blockDim.x + threadIdx.x;
    if (t < EIN) {
        atomicAdd(&iso[isrc[t]], 1.f);
        atomicAdd(&idegi[idst[t]], 1);
    } else if (t < EIN + ECN) {
        atomicAdd(&idegc[cdst[t - EIN]], 1);
    }
}
__global__ void inv_both(float* iso, const int* __restrict__ idegi, float* isi) {
    int i = blockIdx.x * blockDim.x + threadIdx.x;
    if (i >= NN) return;
    iso[i] = rsqrtf(fmaxf(iso[i], 1.f));
    isi[i] = rsqrtf(fmaxf((float)idegi[i], 1.f));
}

// -------- dual 3-stage exclusive scan --------
__global__ void scan1dual(const int* __restrict__ in1, const int* __restrict__ in2,
                          int* out1, int* out2, int* bsum, int n) {
    __shared__ int sh1[256], sh2[256];
    int i = blockIdx.x * 256 + threadIdx.x;
    int v1 = (i < n) ? in1[i] : 0;
    int v2 = (i < n) ? in2[i] : 0;
    sh1[threadIdx.x] = v1; sh2[threadIdx.x] = v2;
    __syncthreads();
    for (int off = 1; off < 256; off <<= 1) {
        int t1 = (threadIdx.x >= off) ? sh1[threadIdx.x - off] : 0;
        int t2 = (threadIdx.x >= off) ? sh2[threadIdx.x - off] : 0;
        __syncthreads();
        sh1[threadIdx.x] += t1; sh2[threadIdx.x] += t2;
        __syncthreads();
    }
    if (i < n) { out1[i] = sh1[threadIdx.x] - v1; out2[i] = sh2[threadIdx.x] - v2; }
    if (threadIdx.x == 255) {
        bsum[blockIdx.x] = sh1[255];
        bsum[512 + blockIdx.x] = sh2[255];
    }
}
__global__ void scan2dual(int* bsum, int nb) {
    __shared__ int sh[512];
    int t = threadIdx.x;
    for (int a = 0; a < 2; a++) {
        int* bs = bsum + a * 512;
        int v = (t < nb) ? bs[t] : 0;
        sh[t] = v;
        __syncthreads();
        for (int off = 1; off < 512; off <<= 1) {
            int x = (t >= off) ? sh[t - off] : 0;
            __syncthreads();
            sh[t] += x;
            __syncthreads();
        }
        if (t < nb) bs[t] = sh[t] - v;
        __syncthreads();
    }
}
__global__ void scan3dual(int* out1, int* out2, const int* __restrict__ bsum,
                          int* cur1, int* cur2, int n) {
    int i = blockIdx.x * 256 + threadIdx.x;
    if (i >= n) return;
    int r1 = out1[i] + bsum[blockIdx.x];
    int r2 = out2[i] + bsum[512 + blockIdx.x];
    out1[i] = r1; out2[i] = r2;
    cur1[i] = r1; cur2[i] = r2;
}
__global__ void scatter_dual(const int* __restrict__ isrc, const int* __restrict__ idst,
                             const int* __restrict__ csrc, const int* __restrict__ cdst,
                             int* curi, int* curc, int* ci, int* ccol) {
    int t = blockIdx.x * blockDim.x + threadIdx.x;
    if (t < EIN) {
        int p = atomicAdd(&curi[idst[t]], 1);
        ci[p] = isrc[t];
    } else if (t < EIN + ECN) {
        int e = t - EIN;
        int p = atomicAdd(&curc[cdst[e]], 1);
        ccol[p] = csrc[e];
    }
}

// -------- weight prep --------
__global__ void prep_w(const float* __restrict__ Wgc, const float* __restrict__ Wgat,
                       const float* __restrict__ s, int K, float* __restrict__ Wp)
{
    int i = blockIdx.x * 256 + threadIdx.x;
    if (i >= K * 256) return;
    int k = i >> 8, j = i & 255;
    float sv = s ? s[k] : 1.f;
    float w = (j < 128) ? Wgc[k * 128 + j] : Wgat[k * 128 + j - 128];
    Wp[i] = to_tf32(sv * w);
}
__global__ __launch_bounds__(128) void prep_c(
    const float* __restrict__ Wgc, const float* __restrict__ Wgat,
    const float* __restrict__ b, int K, float* __restrict__ cvec)
{
    __shared__ float sh[128];
    int j = blockIdx.x;
    int t = threadIdx.x;
    float acc = 0.f;
    if (b) {
        const float* W = (j < 128) ? (Wgc + j) : (Wgat + j - 128);
        for (int k = t; k < K; k += 128)
            acc += b[k] * W[(size_t)k * 128];
    }
    sh[t] = acc;
    __syncthreads();
    for (int off = 64; off; off >>= 1) {
        if (t < off) sh[t] += sh[t + off];
        __syncthreads();
    }
    if (t == 0) cvec[j] = sh[0];
}

// ===================================================================
// Dual-GEMM + fused el/er; outputs stored as fp16 (__half)
// ===================================================================
__global__ __launch_bounds__(512, 1) void gemm_dual_async(
    const float* __restrict__ A, const float* __restrict__ Wp,
    const float* __restrict__ cvec,
    __half* __restrict__ Ca, __half* __restrict__ Cb,
    const float* __restrict__ rowscale,
    const float* __restrict__ alv, const float* __restrict__ arv,
    float* __restrict__ el, float* __restrict__ er,
    int M, int K, int H)
{
    __shared__ float As[3][128 * 16];
    __shared__ float Bs[3][16 * 256];

    const int tid = threadIdx.x;
    const int lane = tid & 31;
    const int wid = tid >> 5;
    const int wm = wid & 3;
    const int wn = wid >> 2;
    const int row0 = blockIdx.x * 128;
    const int iters = K >> 4;

    float acc[2][8][4];
#pragma unroll
    for (int i = 0; i < 2; i++)
#pragma unroll
        for (int j = 0; j < 8; j++)
#pragma unroll
            for (int q = 0; q < 4; q++) acc[i][j][q] = 0.f;

    const int ar_ = tid >> 2, akg = tid & 3;
    const int a_soff = ar_ * 16 + ((akg * 4) ^ (4 * (ar_ & 3)));
    const int a_sz = (row0 + ar_ < M) ? 16 : 0;
    const float* a_src_base = A + (size_t)(row0 + ar_) * K + akg * 4;

    auto loadTile = [&](int it) {
        int buf = it % 3;
        int k0 = it * 16;
        cp16((uint32_t)__cvta_generic_to_shared(&As[buf][a_soff]), a_src_base + k0, a_sz);
#pragma unroll
        for (int i = 0; i < 2; i++) {
            int l = i * 512 + tid;
            int k = l >> 6, n4 = (l & 63) * 4;
            uint32_t dst = (uint32_t)__cvta_generic_to_shared(
                &Bs[buf][k * 256 + (n4 ^ (8 * (k & 3)))]);
            cp16(dst, Wp + (size_t)(k0 + k) * 256 + n4, 16);
        }
        asm volatile("cp.async.commit_group;" ::: "memory");
    };

    loadTile(0);
    if (iters > 1) loadTile(1);
    else asm volatile("cp.async.commit_group;" ::: "memory");

    for (int it = 0; it < iters; ++it) {
        asm volatile("cp.async.wait_group 1;" ::: "memory");
        __syncthreads();
        if (it + 2 < iters) loadTile(it + 2);
        else asm volatile("cp.async.commit_group;" ::: "memory");

        const float* as = As[it % 3];
        const float* bs = Bs[it % 3];

#pragma unroll
        for (int kk = 0; kk < 2; kk++) {
            int k8 = kk * 8;
            uint32_t afr[2][4], bfr[8][2];
#pragma unroll
            for (int i = 0; i < 2; i++) {
                int r = wm * 32 + i * 16 + (lane >> 2);
                int c = k8 + (lane & 3);
                int sw = 4 * (r & 3);
                int r2 = r + 8;
                int sw2 = 4 * (r2 & 3);
                afr[i][0] = __float_as_uint(to_tf32(as[r * 16 + (c ^ sw)]));
                afr[i][1] = __float_as_uint(to_tf32(as[r2 * 16 + (c ^ sw2)]));
                afr[i][2] = __float_as_uint(to_tf32(as[r * 16 + ((c + 4) ^ sw)]));
                afr[i][3] = __float_as_uint(to_tf32(as[r2 * 16 + ((c + 4) ^ sw2)]));
            }
#pragma unroll
            for (int j = 0; j < 8; j++) {
                int n = wn * 64 + j * 8 + (lane >> 2);
                int k = k8 + (lane & 3);
                int k2 = k + 4;
                bfr[j][0] = __float_as_uint(bs[k * 256 + (n ^ (8 * (k & 3)))]);
                bfr[j][1] = __float_as_uint(bs[k2 * 256 + (n ^ (8 * (k2 & 3)))]);
            }
#pragma unroll
            for (int i = 0; i < 2; i++)
#pragma unroll
                for (int j = 0; j < 8; j++)
                    mma_tf32(acc[i][j], afr[i], bfr[j]);
        }
    }

    // ---- store epilogue (fp16 outputs) ----
#pragma unroll
    for (int i = 0; i < 2; i++) {
        int r = row0 + wm * 32 + i * 16 + (lane >> 2);
#pragma unroll
        for (int j = 0; j < 8; j++) {
            int col = wn * 64 + j * 8 + (lane & 3) * 2;
            float c0 = __ldg(cvec + col), c1 = __ldg(cvec + col + 1);
            __half* dstm;
            int c;
            bool isA = (col < 128);
            if (isA) { dstm = Ca; c = col; }
            else     { dstm = Cb; c = col - 128; }
            if (r < M) {
                float s = isA ? __ldg(rowscale + r) : 1.f;
                *(__half2*)(dstm + (size_t)r * 128 + c) =
                    __floats2half2_rn((acc[i][j][0] + c0) * s, (acc[i][j][1] + c1) * s);
            }
            if (r + 8 < M) {
                float s = isA ? __ldg(rowscale + r + 8) : 1.f;
                *(__half2*)(dstm + (size_t)(r + 8) * 128 + c) =
                    __floats2half2_rn((acc[i][j][2] + c0) * s, (acc[i][j][3] + c1) * s);
            }
        }
    }

    // ---- fused el/er from fp32 accumulators (wn >= 2) ----
    if (wn >= 2) {
        const int hmask = (H == 4) ? 1 : 0;
        float pel[4][2], per_[4][2];
#pragma unroll
        for (int rr = 0; rr < 4; rr++) { pel[rr][0] = pel[rr][1] = 0.f; per_[rr][0] = per_[rr][1] = 0.f; }
#pragma unroll
        for (int i = 0; i < 2; i++)
#pragma unroll
            for (int j = 0; j < 8; j++) {
                int col = wn * 64 + j * 8 + (lane & 3) * 2;
                int cf = col - 128;
                float a0 = __ldg(alv + cf), a1 = __ldg(alv + cf + 1);
                float b0 = __ldg(arv + cf), b1 = __ldg(arv + cf + 1);
                float c0 = __ldg(cvec + col), c1 = __ldg(cvec + col + 1);
                int hg = (j >> 2) & hmask;
                float f0 = acc[i][j][0] + c0, f1 = acc[i][j][1] + c1;
                float f2 = acc[i][j][2] + c0, f3 = acc[i][j][3] + c1;
                pel[i * 2 + 0][hg] += f0 * a0 + f1 * a1;
                per_[i * 2 + 0][hg] += f0 * b0 + f1 * b1;
                pel[i * 2 + 1][hg] += f2 * a0 + f3 * a1;
                per_[i * 2 + 1][hg] += f2 * b0 + f3 * b1;
            }
#pragma unroll
        for (int rr = 0; rr < 4; rr++)
#pragma unroll
            for (int hg = 0; hg < 2; hg++) {
                float v = pel[rr][hg];
                v += __shfl_xor_sync(0xffffffffu, v, 1);
                v += __shfl_xor_sync(0xffffffffu, v, 2);
                pel[rr][hg] = v;
                float w = per_[rr][hg];
                w += __shfl_xor_sync(0xffffffffu, w, 1);
                w += __shfl_xor_sync(0xffffffffu, w, 2);
                per_[rr][hg] = w;
            }
        if ((lane & 3) == 0) {
#pragma unroll
            for (int rr = 0; rr < 4; rr++) {
                int row = row0 + wm * 32 + (rr >> 1) * 16 + (lane >> 2) + (rr & 1) * 8;
                if (row < M) {
#pragma unroll
                    for (int hg = 0; hg < 2; hg++) {
                        if (hg > hmask) break;
                        int h = (H == 4) ? ((wn - 2) * 2 + hg) : 0;
                        atomicAdd(&el[(size_t)row * H + h], pel[rr][hg]);
                        atomicAdd(&er[(size_t)row * H + h], per_[rr][hg]);
                    }
                }
            }
        }
    }
}

// -------- per-node softmax: warp-per-node grid-stride, alpha in CSR order --------
template<int H>
__global__ __launch_bounds__(128) void gat_ms_alpha(
    const float* __restrict__ el, const float* __restrict__ er,
    const int* __restrict__ rpc, const int* __restrict__ degc,
    const int* __restrict__ ccol, float* __restrict__ alpha, float* att)
{
    const int lane = threadIdx.x & 31;
    const int warp = (blockIdx.x * blockDim.x + threadIdx.x) >> 5;
    const int nwarps = (gridDim.x * blockDim.x) >> 5;
    const float4* el4 = (const float4*)el;
    const float4* er4 = (const float4*)er;

    for (int n = warp; n < NN; n += nwarps) {
        int c0 = __ldg(rpc + n), deg = __ldg(degc + n);
        if (deg == 0) continue;
        int cend = c0 + deg;

        if (H == 4) {
            float4 ern = __ldg(er4 + n);
            float m0 = -1e30f, m1 = -1e30f, m2 = -1e30f, m3 = -1e30f;
            float s0 = 0.f, s1 = 0.f, s2 = 0.f, s3 = 0.f;
            for (int j = c0 + lane; j < cend; j += 32) {
                int sn = __ldg(ccol + j);
                float4 e4 = __ldg(el4 + sn);
                float e0 = leakyr(e4.x + ern.x), e1 = leakyr(e4.y + ern.y);
                float e2 = leakyr(e4.z + ern.z), e3 = leakyr(e4.w + ern.w);
                if (e0 > m0) { s0 *= __expf(m0 - e0); m0 = e0; } s0 += __expf(e0 - m0);
                if (e1 > m1) { s1 *= __expf(m1 - e1); m1 = e1; } s1 += __expf(e1 - m1);
                if (e2 > m2) { s2 *= __expf(m2 - e2); m2 = e2; } s2 += __expf(e2 - m2);
                if (e3 > m3) { s3 *= __expf(m3 - e3); m3 = e3; } s3 += __expf(e3 - m3);
            }
#pragma unroll
            for (int off = 16; off; off >>= 1) {
                float mo, so, mm;
                mo = __shfl_xor_sync(0xffffffffu, m0, off); so = __shfl_xor_sync(0xffffffffu, s0, off);
                mm = fmaxf(m0, mo); s0 = s0 * __expf(m0 - mm) + so * __expf(mo - mm); m0 = mm;
                mo = __shfl_xor_sync(0xffffffffu, m1, off); so = __shfl_xor_sync(0xffffffffu, s1, off);
                mm = fmaxf(m1, mo); s1 = s1 * __expf(m1 - mm) + so * __expf(mo - mm); m1 = mm;
                mo = __shfl_xor_sync(0xffffffffu, m2, off); so = __shfl_xor_sync(0xffffffffu, s2, off);
                mm = fmaxf(m2, mo); s2 = s2 * __expf(m2 - mm) + so * __expf(mo - mm); m2 = mm;
                mo = __shfl_xor_sync(0xffffffffu, m3, off); so = __shfl_xor_sync(0xffffffffu, s3, off);
                mm = fmaxf(m3, mo); s3 = s3 * __expf(m3 - mm) + so * __expf(mo - mm); m3 = mm;
            }
            float i0 = 1.f / s0, i1 = 1.f / s1, i2 = 1.f / s2, i3 = 1.f / s3;
            for (int j = c0 + lane; j < cend; j += 32) {
                int sn = __ldg(ccol + j);
                float4 e4 = __ldg(el4 + sn);
                float4 o;
                o.x = __expf(leakyr(e4.x + ern.x) - m0) * i0;
                o.y = __expf(leakyr(e4.y + ern.y) - m1) * i1;
                o.z = __expf(leakyr(e4.z + ern.z) - m2) * i2;
                o.w = __expf(leakyr(e4.w + ern.w) - m3) * i3;
                ((float4*)alpha)[j] = o;
            }
        } else {
            float ern = __ldg(er + n);
            float m = -1e30f, s = 0.f;
            for (int j = c0 + lane; j < cend; j += 32) {
                int sn = __ldg(ccol + j);
                float e = leakyr(__ldg(el + sn) + ern);
                if (e > m) { s *= __expf(m - e); m = e; }
                s += __expf(e - m);
            }
#pragma unroll
            for (int off = 16; off; off >>= 1) {
                float mo = __shfl_xor_sync(0xffffffffu, m, off);
                float so = __shfl_xor_sync(0xffffffffu, s, off);
                float mm = fmaxf(m, mo);
                s = s * __expf(m - mm) + so * __expf(mo - mm);
                m = mm;
            }
            float inv = 1.f / s;
            for (int j = c0 + lane; j < cend; j += 32) {
                int sn = __ldg(ccol + j);
                float e = leakyr(__ldg(el + sn) + ern);
                float a = __expf(e - m) * inv;
                alpha[j] = a;
                atomicAdd(&att[sn], a);
            }
        }
    }
}

// ===================================================================
// Fused layer — EXACT R8 structure (2048 blocks x 128 thr, scalar
// per-channel loads), but gathers fp16 values (half the bytes).
// ===================================================================
template<int H, int DO_LEAKY>
__global__ __launch_bounds__(128) void layer_fused(
    const __half* __restrict__ xw, const __half* __restrict__ f,
    const float* __restrict__ alpha, const float* __restrict__ isi,
    const int* __restrict__ rpi, const int* __restrict__ degi, const int* __restrict__ ci,
    const int* __restrict__ rpc, const int* __restrict__ degc, const int* __restrict__ ccol,
    const float* __restrict__ bgc, const float* __restrict__ bga,
    float* __restrict__ z, float* __restrict__ bnsum, float* __restrict__ bnsq)
{
    const int ch = threadIdx.x;
    const int h = (H == 1) ? 0 : (ch >> 5);
    const float bc = __ldg(bgc + ch) + __ldg(bga + ch);
    float ls = 0.f, lq = 0.f;

    for (int n = blockIdx.x; n < NN; n += gridDim.x) {
        float a = 0.f;
        int j = __ldg(rpi + n);
        int bend = j + __ldg(degi + n);
        for (; j + 4 <= bend; j += 4) {
            int s0 = __ldg(ci + j), s1 = __ldg(ci + j + 1);
            int s2 = __ldg(ci + j + 2), s3 = __ldg(ci + j + 3);
            float v0 = __half2float(__ldg(xw + (size_t)s0 * 128 + ch));
            float v1 = __half2float(__ldg(xw + (size_t)s1 * 128 + ch));
            float v2 = __half2float(__ldg(xw + (size_t)s2 * 128 + ch));
            float v3 = __half2float(__ldg(xw + (size_t)s3 * 128 + ch));
            a += (v0 + v1) + (v2 + v3);
        }
        for (; j < bend; j++)
            a += __half2float(__ldg(xw + (size_t)__ldg(ci + j) * 128 + ch));

        float g = 0.f;
        int k = __ldg(rpc + n);
        int cend = k + __ldg(degc + n);
        for (; k + 4 <= cend; k += 4) {
            int s0 = __ldg(ccol + k), s1 = __ldg(ccol + k + 1);
            int s2 = __ldg(ccol + k + 2), s3 = __ldg(ccol + k + 3);
            float a0 = __ldg(alpha + (size_t)(k + 0) * H + h);
            float a1 = __ldg(alpha + (size_t)(k + 1) * H + h);
            float a2 = __ldg(alpha + (size_t)(k + 2) * H + h);
            float a3 = __ldg(alpha + (size_t)(k + 3) * H + h);
            float v0 = __half2float(__ldg(f + (size_t)s0 * 128 + ch));
            float v1 = __half2float(__ldg(f + (size_t)s1 * 128 + ch));
            float v2 = __half2float(__ldg(f + (size_t)s2 * 128 + ch));
            float v3 = __half2float(__ldg(f + (size_t)s3 * 128 + ch));
            g += a0 * v0 + a1 * v1 + a2 * v2 + a3 * v3;
        }
        for (; k < cend; k++) {
            int s0 = __ldg(ccol + k);
            g += __ldg(alpha + (size_t)k * H + h) * __half2float(__ldg(f + (size_t)s0 * 128 + ch));
        }

        float v = a * __ldg(isi + n) + g + bc;
        if (DO_LEAKY) v = leakyr(v);
        z[(size_t)n * 128 + ch] = v;
        ls += v;
        lq += v * v;
    }
    atomicAdd(&bnsum[ch], ls);
    atomicAdd(&bnsq[ch], lq);
}

__global__ void bn_prep(const float* bnsum, const float* bnsq, const float* __restrict__ g,
                        const float* __restrict__ be, float* scale, float* shift)
{
    int c = threadIdx.x;
    if (c >= CC) return;
    float mu = bnsum[c] / (float)NN;
    float var = bnsq[c] / (float)NN - mu * mu;
    float sc = g[c] * rsqrtf(var + 1e-5f);
    scale[c] = sc;
    shift[c] = be[c] - mu * sc;
}

// -------- pooling (layer-3 BN affine fused) --------
__global__ void pool_kernel(const float* __restrict__ z, const float* __restrict__ scale,
                            const float* __restrict__ shift, const float* __restrict__ att,
                            const int* __restrict__ gid, float* gsum)
{
    int idx = blockIdx.x * blockDim.x + threadIdx.x;
    if (idx >= NN * 128) return;
    int n = idx >> 7, ch = idx & 127;
    float v = z[idx] * scale[ch] + shift[ch];
    atomicAdd(&gsum[gid[n] * 128 + ch], v * att[n]);
}
__global__ void gcnt_kernel(const int* __restrict__ gid, float* gcnt) {
    int n = blockIdx.x * blockDim.x + threadIdx.x;
    if (n < NN) atomicAdd(&gcnt[gid[n]], 1.f);
}
__global__ void out_kernel(const float* __restrict__ gsum, const float* __restrict__ gcnt,
                           const float* __restrict__ att, float* __restrict__ out)
{
    int i = blockIdx.x * blockDim.x + threadIdx.x;
    if (i < GN * 128) {
        out[i] = gsum[i] / fmaxf(gcnt[i >> 7], 1.f);
    } else if (i < GN * 128 + NN) {
        out[i] = att[i - GN * 128];
    }
}

static inline int cdiv(int a, int b) { return (a + b - 1) / b; }

extern "C" void kernel_launch(void* const* d_in, const int* in_sizes, int n_in,
                              void* d_out, int out_size)
{
    (void)in_sizes; (void)n_in; (void)out_size;
    const float* feat = (const float*)d_in[0];
    const int* isrc = (const int*)d_in[1];
    const int* idst = (const int*)d_in[2];
    const int* csrc = (const int*)d_in[3];
    const int* cdst = (const int*)d_in[4];
    const int* gid  = (const int*)d_in[5];
    const float* Wgc[3]  = {(const float*)d_in[6],  (const float*)d_in[12], (const float*)d_in[18]};
    const float* bgc[3]  = {(const float*)d_in[7],  (const float*)d_in[13], (const float*)d_in[19]};
    const float* Wgat[3] = {(const float*)d_in[8],  (const float*)d_in[14], (const float*)d_in[20]};
    const float* al[3]   = {(const float*)d_in[9],  (const float*)d_in[15], (const float*)d_in[21]};
    const float* ar[3]   = {(const float*)d_in[10], (const float*)d_in[16], (const float*)d_in[22]};
    const float* bga[3]  = {(const float*)d_in[11], (const float*)d_in[17], (const float*)d_in[23]};
    const float* gam[3]  = {(const float*)d_in[24], (const float*)d_in[26], (const float*)d_in[28]};
    const float* bet[3]  = {(const float*)d_in[25], (const float*)d_in[27], (const float*)d_in[29]};
    float* out = (float*)d_out;

    __half *xw, *f;
    float *z, *el, *er, *alpha, *wp, *cvec;
    float *iso, *isi, *att, *gsum, *gcnt, *bnsum, *bnsq, *bnscale, *bnshift;
    int *idegi, *idegc, *rpi, *rpc, *curi, *curc, *bsum, *ci, *ccol;
    cudaGetSymbolAddress((void**)&xw, g_xw);
    cudaGetSymbolAddress((void**)&f, g_f);
    cudaGetSymbolAddress((void**)&z, g_z);
    cudaGetSymbolAddress((void**)&el, g_el);
    cudaGetSymbolAddress((void**)&er, g_er);
    cudaGetSymbolAddress((void**)&alpha, g_alpha);
    cudaGetSymbolAddress((void**)&wp, g_wp);
    cudaGetSymbolAddress((void**)&cvec, g_cvec);
    cudaGetSymbolAddress((void**)&iso, g_iso);
    cudaGetSymbolAddress((void**)&isi, g_isi);
    cudaGetSymbolAddress((void**)&att, g_att);
    cudaGetSymbolAddress((void**)&gsum, g_gsum);
    cudaGetSymbolAddress((void**)&gcnt, g_gcnt);
    cudaGetSymbolAddress((void**)&bnsum, g_bnsum);
    cudaGetSymbolAddress((void**)&bnsq, g_bnsq);
    cudaGetSymbolAddress((void**)&bnscale, g_bnscale);
    cudaGetSymbolAddress((void**)&bnshift, g_bnshift);
    cudaGetSymbolAddress((void**)&idegi, g_idegi);
    cudaGetSymbolAddress((void**)&idegc, g_idegc);
    cudaGetSymbolAddress((void**)&rpi, g_rpi);
    cudaGetSymbolAddress((void**)&rpc, g_rpc);
    cudaGetSymbolAddress((void**)&curi, g_curi);
    cudaGetSymbolAddress((void**)&curc, g_curc);
    cudaGetSymbolAddress((void**)&bsum, g_bsum);
    cudaGetSymbolAddress((void**)&ci, g_ci);
    cudaGetSymbolAddress((void**)&ccol, g_ccol);

    const int NB = cdiv(NN, 256);

    prep_w<<<cdiv(FDIM * 256, 256), 256>>>(Wgc[0], Wgat[0], nullptr, FDIM, wp);
    prep_c<<<256, 128>>>(Wgc[0], Wgat[0], nullptr, FDIM, cvec);
    init_zero<<<cdiv(NN, 256), 256>>>(iso, idegi, idegc, att);
    edge_deg<<<cdiv(EIN + ECN, 256), 256>>>(isrc, idst, cdst, iso, idegi, idegc);
    inv_both<<<cdiv(NN, 256), 256>>>(iso, idegi, isi);

    // CSR build (dual)
    scan1dual<<<NB, 256>>>(idegi, idegc, rpi, rpc, bsum, NN);
    scan2dual<<<1, 512>>>(bsum, NB);
    scan3dual<<<NB, 256>>>(rpi, rpc, bsum, curi, curc, NN);
    scatter_dual<<<cdiv(EIN + ECN, 256), 256>>>(isrc, idst, csrc, cdst, curi, curc, ci, ccol);

    const int Hs[3] = {4, 4, 1};
    for (int L = 0; L < 3; L++) {
        int K = (L == 0) ? FDIM : CC;
        int H = Hs[L];

        if (L > 0) {
            prep_w<<<cdiv(K * 256, 256), 256>>>(Wgc[L], Wgat[L], bnscale, K, wp);
            prep_c<<<256, 128>>>(Wgc[L], Wgat[L], bnshift, K, cvec);
        }
        zero_layer<<<cdiv(NN * 4, 256), 256>>>(el, er, bnsum, bnsq);
        gemm_dual_async<<<cdiv(NN, 128), 512>>>((L == 0) ? feat : z, wp, cvec, xw, f,
                                                iso, al[L], ar[L], el, er, NN, K, H);

        if (H == 4)
            gat_ms_alpha<4><<<2048, 128>>>(el, er, rpc, idegc, ccol, alpha, nullptr);
        else
            gat_ms_alpha<1><<<2048, 128>>>(el, er, rpc, idegc, ccol, alpha, att);

        if (L < 2)
            layer_fused<4, 1><<<2048, 128>>>(xw, f, alpha, isi, rpi, idegi, ci,
                                             rpc, idegc, ccol, bgc[L], bga[L],
                                             z, bnsum, bnsq);
        else
            layer_fused<1, 0><<<2048, 128>>>(xw, f, alpha, isi, rpi, idegi, ci,
                                             rpc, idegc, ccol, bgc[L], bga[L],
                                             z, bnsum, bnsq);

        bn_prep<<<1, 128>>>(bnsum, bnsq, gam[L], bet[L], bnscale, bnshift);
    }

    // ---- pooling (bn affine fused) ----
    fill_kernel<<<cdiv(GN * CC, 256), 256>>>(gsum, 0.f, GN * CC);
    fill_kernel<<<cdiv(GN, 256), 256>>>(gcnt, 0.f, GN);
    gcnt_kernel<<<cdiv(NN, 256), 256>>>(gid, gcnt);
    pool_kernel<<<cdiv(NN * CC, 256), 256>>>(z, bnscale, bnshift, att, gid, gsum);
    out_kernel<<<cdiv(GN * CC + NN, 256), 256>>>(gsum, gcnt, att, out);
}

// round 13
// speedup vs baseline: 1.3271x; 1.0587x over previous
#include <cuda_runtime.h>
#include <cuda_fp16.h>
#include <cstdint>

#define NN  100000
#define EIN 1600000
#define ECN 800000
#define GN  2000
#define FDIM 512
#define CC  128

// -------- scratch (device globals; no allocation) --------
__device__ __half g_xw[NN*CC];
__device__ __half g_f[NN*CC];
__device__ float g_z[NN*CC];
__device__ float g_el[NN*4];
__device__ float g_er[NN*4];
__device__ float g_alpha[ECN*4];
__device__ float g_iso[NN];
__device__ float g_isi[NN];
__device__ float g_att[NN];
__device__ float g_gsum[GN*CC];
__device__ float g_gcnt[GN];
__device__ float g_bnsum[CC];
__device__ float g_bnsq[CC];
__device__ float g_bnscale[CC];
__device__ float g_bnshift[CC];
__device__ __half g_wp[256*FDIM];   // transposed [n][k], fp16
__device__ float g_cvec[256];
// CSR scratch
__device__ int g_idegi[NN];
__device__ int g_idegc[NN];
__device__ int g_rpi[NN];
__device__ int g_rpc[NN];
__device__ int g_curi[NN];
__device__ int g_curc[NN];
__device__ int g_bsum[1024];
__device__ int g_ci[EIN];
__device__ int g_ccol[ECN];

__device__ __forceinline__ float leakyr(float x) { return x >= 0.f ? x : 0.2f * x; }

__device__ __forceinline__ void mma_f16(float* d, const uint32_t* a, const uint32_t* b) {
    asm volatile(
        "mma.sync.aligned.m16n8k16.row.col.f32.f16.f16.f32 "
        "{%0,%1,%2,%3}, {%4,%5,%6,%7}, {%8,%9}, {%0,%1,%2,%3};"
        : "+f"(d[0]), "+f"(d[1]), "+f"(d[2]), "+f"(d[3])
        : "r"(a[0]), "r"(a[1]), "r"(a[2]), "r"(a[3]), "r"(b[0]), "r"(b[1]));
}

__device__ __forceinline__ uint32_t packh2(float lo, float hi) {
    __half2 h = __floats2half2_rn(lo, hi);
    return *(uint32_t*)&h;
}

__device__ __forceinline__ void cp16(uint32_t dst, const void* src, int sz) {
    asm volatile("cp.async.cg.shared.global [%0], [%1], 16, %2;"
                 :: "r"(dst), "l"(src), "r"(sz) : "memory");
}

// -------- utility --------
__global__ void fill_kernel(float* p, float v, int n) {
    int i = blockIdx.x * blockDim.x + threadIdx.x;
    if (i < n) p[i] = v;
}
__global__ void zero_layer(float* el, float* er, float* bnsum, float* bnsq) {
    int i = blockIdx.x * blockDim.x + threadIdx.x;
    if (i < NN * 4) { el[i] = 0.f; er[i] = 0.f; }
    if (i < CC) { bnsum[i] = 0.f; bnsq[i] = 0.f; }
}
__global__ void init_zero(float* iso, int* idegi, int* idegc, float* att) {
    int i = blockIdx.x * blockDim.x + threadIdx.x;
    if (i < NN) { iso[i] = 0.f; idegi[i] = 0; idegc[i] = 0; att[i] = 0.f; }
}
__global__ void edge_deg(const int* __restrict__ isrc, const int* __restrict__ idst,
                         const int* __restrict__ cdst, float* iso, int* idegi, int* idegc) {
    int t = blockIdx.x * blockDim.x + threadIdx.x;
    if (t < EIN) {
        atomicAdd(&iso[isrc[t]], 1.f);
        atomicAdd(&idegi[idst[t]], 1);
    } else if (t < EIN + ECN) {
        atomicAdd(&idegc[cdst[t - EIN]], 1);
    }
}
__global__ void inv_both(float* iso, const int* __restrict__ idegi, float* isi) {
    int i = blockIdx.x * blockDim.x + threadIdx.x;
    if (i >= NN) return;
    iso[i] = rsqrtf(fmaxf(iso[i], 1.f));
    isi[i] = rsqrtf(fmaxf((float)idegi[i], 1.f));
}

// -------- dual 3-stage exclusive scan --------
__global__ void scan1dual(const int* __restrict__ in1, const int* __restrict__ in2,
                          int* out1, int* out2, int* bsum, int n) {
    __shared__ int sh1[256], sh2[256];
    int i = blockIdx.x * 256 + threadIdx.x;
    int v1 = (i < n) ? in1[i] : 0;
    int v2 = (i < n) ? in2[i] : 0;
    sh1[threadIdx.x] = v1; sh2[threadIdx.x] = v2;
    __syncthreads();
    for (int off = 1; off < 256; off <<= 1) {
        int t1 = (threadIdx.x >= off) ? sh1[threadIdx.x - off] : 0;
        int t2 = (threadIdx.x >= off) ? sh2[threadIdx.x - off] : 0;
        __syncthreads();
        sh1[threadIdx.x] += t1; sh2[threadIdx.x] += t2;
        __syncthreads();
    }
    if (i < n) { out1[i] = sh1[threadIdx.x] - v1; out2[i] = sh2[threadIdx.x] - v2; }
    if (threadIdx.x == 255) {
        bsum[blockIdx.x] = sh1[255];
        bsum[512 + blockIdx.x] = sh2[255];
    }
}
__global__ void scan2dual(int* bsum, int nb) {
    __shared__ int sh[512];
    int t = threadIdx.x;
    for (int a = 0; a < 2; a++) {
        int* bs = bsum + a * 512;
        int v = (t < nb) ? bs[t] : 0;
        sh[t] = v;
        __syncthreads();
        for (int off = 1; off < 512; off <<= 1) {
            int x = (t >= off) ? sh[t - off] : 0;
            __syncthreads();
            sh[t] += x;
            __syncthreads();
        }
        if (t < nb) bs[t] = sh[t] - v;
        __syncthreads();
    }
}
__global__ void scan3dual(int* out1, int* out2, const int* __restrict__ bsum,
                          int* cur1, int* cur2, int n) {
    int i = blockIdx.x * 256 + threadIdx.x;
    if (i >= n) return;
    int r1 = out1[i] + bsum[blockIdx.x];
    int r2 = out2[i] + bsum[512 + blockIdx.x];
    out1[i] = r1; out2[i] = r2;
    cur1[i] = r1; cur2[i] = r2;
}
__global__ void scatter_dual(const int* __restrict__ isrc, const int* __restrict__ idst,
                             const int* __restrict__ csrc, const int* __restrict__ cdst,
                             int* curi, int* curc, int* ci, int* ccol) {
    int t = blockIdx.x * blockDim.x + threadIdx.x;
    if (t < EIN) {
        int p = atomicAdd(&curi[idst[t]], 1);
        ci[p] = isrc[t];
    } else if (t < EIN + ECN) {
        int e = t - EIN;
        int p = atomicAdd(&curc[cdst[e]], 1);
        ccol[p] = csrc[e];
    }
}

// -------- weight prep: Wp[n][k] = fp16(s[k]*W[k][n]) (transposed) --------
__global__ void prep_w(const float* __restrict__ Wgc, const float* __restrict__ Wgat,
                       const float* __restrict__ s, int K, __half* __restrict__ Wp)
{
    int i = blockIdx.x * 256 + threadIdx.x;
    if (i >= K * 256) return;
    int k = i >> 8, j = i & 255;
    float sv = s ? s[k] : 1.f;
    float w = (j < 128) ? Wgc[k * 128 + j] : Wgat[k * 128 + j - 128];
    Wp[(size_t)j * K + k] = __float2half(sv * w);
}
__global__ __launch_bounds__(128) void prep_c(
    const float* __restrict__ Wgc, const float* __restrict__ Wgat,
    const float* __restrict__ b, int K, float* __restrict__ cvec)
{
    __shared__ float sh[128];
    int j = blockIdx.x;
    int t = threadIdx.x;
    float acc = 0.f;
    if (b) {
        const float* W = (j < 128) ? (Wgc + j) : (Wgat + j - 128);
        for (int k = t; k < K; k += 128)
            acc += b[k] * W[(size_t)k * 128];
    }
    sh[t] = acc;
    __syncthreads();
    for (int off = 64; off; off >>= 1) {
        if (t < off) sh[t] += sh[t + off];
        __syncthreads();
    }
    if (t == 0) cvec[j] = sh[0];
}

// ===================================================================
// Dual-GEMM, fp16 m16n8k16 mma, fp32 accum, cp.async 3-stage, BK=16
// A fp32 in smem (swizzled), packed to half2 at frag load.
// B fp16 smem [n=256][k=16] with 16B-granule XOR swizzle.
// Epilogue identical to R12 (fp16 stores + fused el/er).
// ===================================================================
__global__ __launch_bounds__(512, 1) void gemm_dual_async(
    const float* __restrict__ A, const __half* __restrict__ Wp,
    const float* __restrict__ cvec,
    __half* __restrict__ Ca, __half* __restrict__ Cb,
    const float* __restrict__ rowscale,
    const float* __restrict__ alv, const float* __restrict__ arv,
    float* __restrict__ el, float* __restrict__ er,
    int M, int K, int H)
{
    __shared__ __align__(16) float As[3][128 * 16];
    __shared__ __align__(16) __half Bs[3][256 * 16];

    const int tid = threadIdx.x;
    const int lane = tid & 31;
    const int wid = tid >> 5;
    const int wm = wid & 3;
    const int wn = wid >> 2;
    const int row0 = blockIdx.x * 128;
    const int iters = K >> 4;

    float acc[2][8][4];
#pragma unroll
    for (int i = 0; i < 2; i++)
#pragma unroll
        for (int j = 0; j < 8; j++)
#pragma unroll
            for (int q = 0; q < 4; q++) acc[i][j][q] = 0.f;

    const int ar_ = tid >> 2, akg = tid & 3;
    const int a_soff = ar_ * 16 + ((akg * 4) ^ (4 * (ar_ & 3)));
    const int a_sz = (row0 + ar_ < M) ? 16 : 0;
    const float* a_src_base = A + (size_t)(row0 + ar_) * K + akg * 4;

    // B load: thread covers row n = tid>>1, granule gsel = tid&1 (8 halves = 16B)
    const int bn = tid >> 1, bg = tid & 1;
    const int b_soff = bn * 16 + ((bg ^ (bn & 1)) << 3);
    const __half* b_src_base = Wp + (size_t)bn * K + bg * 8;

    auto loadTile = [&](int it) {
        int buf = it % 3;
        int k0 = it * 16;
        cp16((uint32_t)__cvta_generic_to_shared(&As[buf][a_soff]), a_src_base + k0, a_sz);
        cp16((uint32_t)__cvta_generic_to_shared(&Bs[buf][b_soff]), b_src_base + k0, 16);
        asm volatile("cp.async.commit_group;" ::: "memory");
    };

    loadTile(0);
    if (iters > 1) loadTile(1);
    else asm volatile("cp.async.commit_group;" ::: "memory");

    for (int it = 0; it < iters; ++it) {
        asm volatile("cp.async.wait_group 1;" ::: "memory");
        __syncthreads();
        if (it + 2 < iters) loadTile(it + 2);
        else asm volatile("cp.async.commit_group;" ::: "memory");

        const float* as = As[it % 3];
        const __half* bs = Bs[it % 3];

        uint32_t afr[2][4], bfr[8][2];
        const int c = (lane & 3) * 2;
#pragma unroll
        for (int i = 0; i < 2; i++) {
            int r = wm * 32 + i * 16 + (lane >> 2);
            int r2 = r + 8;
            int sw = 4 * (r & 3);
            int sw2 = 4 * (r2 & 3);
            float2 f00 = *(const float2*)&as[r * 16 + (c ^ sw)];
            float2 f10 = *(const float2*)&as[r2 * 16 + (c ^ sw2)];
            float2 f01 = *(const float2*)&as[r * 16 + ((c + 8) ^ sw)];
            float2 f11 = *(const float2*)&as[r2 * 16 + ((c + 8) ^ sw2)];
            afr[i][0] = packh2(f00.x, f00.y);
            afr[i][1] = packh2(f10.x, f10.y);
            afr[i][2] = packh2(f01.x, f01.y);
            afr[i][3] = packh2(f11.x, f11.y);
        }
#pragma unroll
        for (int j = 0; j < 8; j++) {
            int n = wn * 64 + j * 8 + (lane >> 2);
            const __half* brow = bs + n * 16;
            int g0 = (0 ^ (n & 1)) << 3;
            int g1 = (1 ^ (n & 1)) << 3;
            bfr[j][0] = *(const uint32_t*)&brow[g0 + c];
            bfr[j][1] = *(const uint32_t*)&brow[g1 + c];
        }
#pragma unroll
        for (int i = 0; i < 2; i++)
#pragma unroll
            for (int j = 0; j < 8; j++)
                mma_f16(acc[i][j], afr[i], bfr[j]);
    }

    // ---- store epilogue (fp16 outputs) ----
#pragma unroll
    for (int i = 0; i < 2; i++) {
        int r = row0 + wm * 32 + i * 16 + (lane >> 2);
#pragma unroll
        for (int j = 0; j < 8; j++) {
            int col = wn * 64 + j * 8 + (lane & 3) * 2;
            float c0 = __ldg(cvec + col), c1 = __ldg(cvec + col + 1);
            __half* dstm;
            int cc;
            bool isA = (col < 128);
            if (isA) { dstm = Ca; cc = col; }
            else     { dstm = Cb; cc = col - 128; }
            if (r < M) {
                float s = isA ? __ldg(rowscale + r) : 1.f;
                *(__half2*)(dstm + (size_t)r * 128 + cc) =
                    __floats2half2_rn((acc[i][j][0] + c0) * s, (acc[i][j][1] + c1) * s);
            }
            if (r + 8 < M) {
                float s = isA ? __ldg(rowscale + r + 8) : 1.f;
                *(__half2*)(dstm + (size_t)(r + 8) * 128 + cc) =
                    __floats2half2_rn((acc[i][j][2] + c0) * s, (acc[i][j][3] + c1) * s);
            }
        }
    }

    // ---- fused el/er from fp32 accumulators (wn >= 2) ----
    if (wn >= 2) {
        const int hmask = (H == 4) ? 1 : 0;
        float pel[4][2], per_[4][2];
#pragma unroll
        for (int rr = 0; rr < 4; rr++) { pel[rr][0] = pel[rr][1] = 0.f; per_[rr][0] = per_[rr][1] = 0.f; }
#pragma unroll
        for (int i = 0; i < 2; i++)
#pragma unroll
            for (int j = 0; j < 8; j++) {
                int col = wn * 64 + j * 8 + (lane & 3) * 2;
                int cf = col - 128;
                float a0 = __ldg(alv + cf), a1 = __ldg(alv + cf + 1);
                float b0 = __ldg(arv + cf), b1 = __ldg(arv + cf + 1);
                float c0 = __ldg(cvec + col), c1 = __ldg(cvec + col + 1);
                int hg = (j >> 2) & hmask;
                float f0 = acc[i][j][0] + c0, f1 = acc[i][j][1] + c1;
                float f2 = acc[i][j][2] + c0, f3 = acc[i][j][3] + c1;
                pel[i * 2 + 0][hg] += f0 * a0 + f1 * a1;
                per_[i * 2 + 0][hg] += f0 * b0 + f1 * b1;
                pel[i * 2 + 1][hg] += f2 * a0 + f3 * a1;
                per_[i * 2 + 1][hg] += f2 * b0 + f3 * b1;
            }
#pragma unroll
        for (int rr = 0; rr < 4; rr++)
#pragma unroll
            for (int hg = 0; hg < 2; hg++) {
                float v = pel[rr][hg];
                v += __shfl_xor_sync(0xffffffffu, v, 1);
                v += __shfl_xor_sync(0xffffffffu, v, 2);
                pel[rr][hg] = v;
                float w = per_[rr][hg];
                w += __shfl_xor_sync(0xffffffffu, w, 1);
                w += __shfl_xor_sync(0xffffffffu, w, 2);
                per_[rr][hg] = w;
            }
        if ((lane & 3) == 0) {
#pragma unroll
            for (int rr = 0; rr < 4; rr++) {
                int row = row0 + wm * 32 + (rr >> 1) * 16 + (lane >> 2) + (rr & 1) * 8;
                if (row < M) {
#pragma unroll
                    for (int hg = 0; hg < 2; hg++) {
                        if (hg > hmask) break;
                        int h = (H == 4) ? ((wn - 2) * 2 + hg) : 0;
                        atomicAdd(&el[(size_t)row * H + h], pel[rr][hg]);
                        atomicAdd(&er[(size_t)row * H + h], per_[rr][hg]);
                    }
                }
            }
        }
    }
}

// -------- per-node softmax: warp-per-node grid-stride, alpha in CSR order --------
template<int H>
__global__ __launch_bounds__(128) void gat_ms_alpha(
    const float* __restrict__ el, const float* __restrict__ er,
    const int* __restrict__ rpc, const int* __restrict__ degc,
    const int* __restrict__ ccol, float* __restrict__ alpha, float* att)
{
    const int lane = threadIdx.x & 31;
    const int warp = (blockIdx.x * blockDim.x + threadIdx.x) >> 5;
    const int nwarps = (gridDim.x * blockDim.x) >> 5;
    const float4* el4 = (const float4*)el;
    const float4* er4 = (const float4*)er;

    for (int n = warp; n < NN; n += nwarps) {
        int c0 = __ldg(rpc + n), deg = __ldg(degc + n);
        if (deg == 0) continue;
        int cend = c0 + deg;

        if (H == 4) {
            float4 ern = __ldg(er4 + n);
            float m0 = -1e30f, m1 = -1e30f, m2 = -1e30f, m3 = -1e30f;
            float s0 = 0.f, s1 = 0.f, s2 = 0.f, s3 = 0.f;
            for (int j = c0 + lane; j < cend; j += 32) {
                int sn = __ldg(ccol + j);
                float4 e4 = __ldg(el4 + sn);
                float e0 = leakyr(e4.x + ern.x), e1 = leakyr(e4.y + ern.y);
                float e2 = leakyr(e4.z + ern.z), e3 = leakyr(e4.w + ern.w);
                if (e0 > m0) { s0 *= __expf(m0 - e0); m0 = e0; } s0 += __expf(e0 - m0);
                if (e1 > m1) { s1 *= __expf(m1 - e1); m1 = e1; } s1 += __expf(e1 - m1);
                if (e2 > m2) { s2 *= __expf(m2 - e2); m2 = e2; } s2 += __expf(e2 - m2);
                if (e3 > m3) { s3 *= __expf(m3 - e3); m3 = e3; } s3 += __expf(e3 - m3);
            }
#pragma unroll
            for (int off = 16; off; off >>= 1) {
                float mo, so, mm;
                mo = __shfl_xor_sync(0xffffffffu, m0, off); so = __shfl_xor_sync(0xffffffffu, s0, off);
                mm = fmaxf(m0, mo); s0 = s0 * __expf(m0 - mm) + so * __expf(mo - mm); m0 = mm;
                mo = __shfl_xor_sync(0xffffffffu, m1, off); so = __shfl_xor_sync(0xffffffffu, s1, off);
                mm = fmaxf(m1, mo); s1 = s1 * __expf(m1 - mm) + so * __expf(mo - mm); m1 = mm;
                mo = __shfl_xor_sync(0xffffffffu, m2, off); so = __shfl_xor_sync(0xffffffffu, s2, off);
                mm = fmaxf(m2, mo); s2 = s2 * __expf(m2 - mm) + so * __expf(mo - mm); m2 = mm;
                mo = __shfl_xor_sync(0xffffffffu, m3, off); so = __shfl_xor_sync(0xffffffffu, s3, off);
                mm = fmaxf(m3, mo); s3 = s3 * __expf(m3 - mm) + so * __expf(mo - mm); m3 = mm;
            }
            float i0 = 1.f / s0, i1 = 1.f / s1, i2 = 1.f / s2, i3 = 1.f / s3;
            for (int j = c0 + lane; j < cend; j += 32) {
                int sn = __ldg(ccol + j);
                float4 e4 = __ldg(el4 + sn);
                float4 o;
                o.x = __expf(leakyr(e4.x + ern.x) - m0) * i0;
                o.y = __expf(leakyr(e4.y + ern.y) - m1) * i1;
                o.z = __expf(leakyr(e4.z + ern.z) - m2) * i2;
                o.w = __expf(leakyr(e4.w + ern.w) - m3) * i3;
                ((float4*)alpha)[j] = o;
            }
        } else {
            float ern = __ldg(er + n);
            float m = -1e30f, s = 0.f;
            for (int j = c0 + lane; j < cend; j += 32) {
                int sn = __ldg(ccol + j);
                float e = leakyr(__ldg(el + sn) + ern);
                if (e > m) { s *= __expf(m - e); m = e; }
                s += __expf(e - m);
            }
#pragma unroll
            for (int off = 16; off; off >>= 1) {
                float mo = __shfl_xor_sync(0xffffffffu, m, off);
                float so = __shfl_xor_sync(0xffffffffu, s, off);
                float mm = fmaxf(m, mo);
                s = s * __expf(m - mm) + so * __expf(mo - mm);
                m = mm;
            }
            float inv = 1.f / s;
            for (int j = c0 + lane; j < cend; j += 32) {
                int sn = __ldg(ccol + j);
                float e = leakyr(__ldg(el + sn) + ern);
                float a = __expf(e - m) * inv;
                alpha[j] = a;
                atomicAdd(&att[sn], a);
            }
        }
    }
}

// ===================================================================
// Fused layer — FROZEN R8/R12 structure (2048 x 128, scalar fp16 gather)
// ===================================================================
template<int H, int DO_LEAKY>
__global__ __launch_bounds__(128) void layer_fused(
    const __half* __restrict__ xw, const __half* __restrict__ f,
    const float* __restrict__ alpha, const float* __restrict__ isi,
    const int* __restrict__ rpi, const int* __restrict__ degi, const int* __restrict__ ci,
    const int* __restrict__ rpc, const int* __restrict__ degc, const int* __restrict__ ccol,
    const float* __restrict__ bgc, const float* __restrict__ bga,
    float* __restrict__ z, float* __restrict__ bnsum, float* __restrict__ bnsq)
{
    const int ch = threadIdx.x;
    const int h = (H == 1) ? 0 : (ch >> 5);
    const float bc = __ldg(bgc + ch) + __ldg(bga + ch);
    float ls = 0.f, lq = 0.f;

    for (int n = blockIdx.x; n < NN; n += gridDim.x) {
        float a = 0.f;
        int j = __ldg(rpi + n);
        int bend = j + __ldg(degi + n);
        for (; j + 4 <= bend; j += 4) {
            int s0 = __ldg(ci + j), s1 = __ldg(ci + j + 1);
            int s2 = __ldg(ci + j + 2), s3 = __ldg(ci + j + 3);
            float v0 = __half2float(__ldg(xw + (size_t)s0 * 128 + ch));
            float v1 = __half2float(__ldg(xw + (size_t)s1 * 128 + ch));
            float v2 = __half2float(__ldg(xw + (size_t)s2 * 128 + ch));
            float v3 = __half2float(__ldg(xw + (size_t)s3 * 128 + ch));
            a += (v0 + v1) + (v2 + v3);
        }
        for (; j < bend; j++)
            a += __half2float(__ldg(xw + (size_t)__ldg(ci + j) * 128 + ch));

        float g = 0.f;
        int k = __ldg(rpc + n);
        int cend = k + __ldg(degc + n);
        for (; k + 4 <= cend; k += 4) {
            int s0 = __ldg(ccol + k), s1 = __ldg(ccol + k + 1);
            int s2 = __ldg(ccol + k + 2), s3 = __ldg(ccol + k + 3);
            float a0 = __ldg(alpha + (size_t)(k + 0) * H + h);
            float a1 = __ldg(alpha + (size_t)(k + 1) * H + h);
            float a2 = __ldg(alpha + (size_t)(k + 2) * H + h);
            float a3 = __ldg(alpha + (size_t)(k + 3) * H + h);
            float v0 = __half2float(__ldg(f + (size_t)s0 * 128 + ch));
            float v1 = __half2float(__ldg(f + (size_t)s1 * 128 + ch));
            float v2 = __half2float(__ldg(f + (size_t)s2 * 128 + ch));
            float v3 = __half2float(__ldg(f + (size_t)s3 * 128 + ch));
            g += a0 * v0 + a1 * v1 + a2 * v2 + a3 * v3;
        }
        for (; k < cend; k++) {
            int s0 = __ldg(ccol + k);
            g += __ldg(alpha + (size_t)k * H + h) * __half2float(__ldg(f + (size_t)s0 * 128 + ch));
        }

        float v = a * __ldg(isi + n) + g + bc;
        if (DO_LEAKY) v = leakyr(v);
        z[(size_t)n * 128 + ch] = v;
        ls += v;
        lq += v * v;
    }
    atomicAdd(&bnsum[ch], ls);
    atomicAdd(&bnsq[ch], lq);
}

__global__ void bn_prep(const float* bnsum, const float* bnsq, const float* __restrict__ g,
                        const float* __restrict__ be, float* scale, float* shift)
{
    int c = threadIdx.x;
    if (c >= CC) return;
    float mu = bnsum[c] / (float)NN;
    float var = bnsq[c] / (float)NN - mu * mu;
    float sc = g[c] * rsqrtf(var + 1e-5f);
    scale[c] = sc;
    shift[c] = be[c] - mu * sc;
}

// -------- pooling (layer-3 BN affine fused) --------
__global__ void pool_kernel(const float* __restrict__ z, const float* __restrict__ scale,
                            const float* __restrict__ shift, const float* __restrict__ att,
                            const int* __restrict__ gid, float* gsum)
{
    int idx = blockIdx.x * blockDim.x + threadIdx.x;
    if (idx >= NN * 128) return;
    int n = idx >> 7, ch = idx & 127;
    float v = z[idx] * scale[ch] + shift[ch];
    atomicAdd(&gsum[gid[n] * 128 + ch], v * att[n]);
}
__global__ void gcnt_kernel(const int* __restrict__ gid, float* gcnt) {
    int n = blockIdx.x * blockDim.x + threadIdx.x;
    if (n < NN) atomicAdd(&gcnt[gid[n]], 1.f);
}
__global__ void out_kernel(const float* __restrict__ gsum, const float* __restrict__ gcnt,
                           const float* __restrict__ att, float* __restrict__ out)
{
    int i = blockIdx.x * blockDim.x + threadIdx.x;
    if (i < GN * 128) {
        out[i] = gsum[i] / fmaxf(gcnt[i >> 7], 1.f);
    } else if (i < GN * 128 + NN) {
        out[i] = att[i - GN * 128];
    }
}

static inline int cdiv(int a, int b) { return (a + b - 1) / b; }

extern "C" void kernel_launch(void* const* d_in, const int* in_sizes, int n_in,
                              void* d_out, int out_size)
{
    (void)in_sizes; (void)n_in; (void)out_size;
    const float* feat = (const float*)d_in[0];
    const int* isrc = (const int*)d_in[1];
    const int* idst = (const int*)d_in[2];
    const int* csrc = (const int*)d_in[3];
    const int* cdst = (const int*)d_in[4];
    const int* gid  = (const int*)d_in[5];
    const float* Wgc[3]  = {(const float*)d_in[6],  (const float*)d_in[12], (const float*)d_in[18]};
    const float* bgc[3]  = {(const float*)d_in[7],  (const float*)d_in[13], (const float*)d_in[19]};
    const float* Wgat[3] = {(const float*)d_in[8],  (const float*)d_in[14], (const float*)d_in[20]};
    const float* al[3]   = {(const float*)d_in[9],  (const float*)d_in[15], (const float*)d_in[21]};
    const float* ar[3]   = {(const float*)d_in[10], (const float*)d_in[16], (const float*)d_in[22]};
    const float* bga[3]  = {(const float*)d_in[11], (const float*)d_in[17], (const float*)d_in[23]};
    const float* gam[3]  = {(const float*)d_in[24], (const float*)d_in[26], (const float*)d_in[28]};
    const float* bet[3]  = {(const float*)d_in[25], (const float*)d_in[27], (const float*)d_in[29]};
    float* out = (float*)d_out;

    __half *xw, *f, *wp;
    float *z, *el, *er, *alpha, *cvec;
    float *iso, *isi, *att, *gsum, *gcnt, *bnsum, *bnsq, *bnscale, *bnshift;
    int *idegi, *idegc, *rpi, *rpc, *curi, *curc, *bsum, *ci, *ccol;
    cudaGetSymbolAddress((void**)&xw, g_xw);
    cudaGetSymbolAddress((void**)&f, g_f);
    cudaGetSymbolAddress((void**)&z, g_z);
    cudaGetSymbolAddress((void**)&el, g_el);
    cudaGetSymbolAddress((void**)&er, g_er);
    cudaGetSymbolAddress((void**)&alpha, g_alpha);
    cudaGetSymbolAddress((void**)&wp, g_wp);
    cudaGetSymbolAddress((void**)&cvec, g_cvec);
    cudaGetSymbolAddress((void**)&iso, g_iso);
    cudaGetSymbolAddress((void**)&isi, g_isi);
    cudaGetSymbolAddress((void**)&att, g_att);
    cudaGetSymbolAddress((void**)&gsum, g_gsum);
    cudaGetSymbolAddress((void**)&gcnt, g_gcnt);
    cudaGetSymbolAddress((void**)&bnsum, g_bnsum);
    cudaGetSymbolAddress((void**)&bnsq, g_bnsq);
    cudaGetSymbolAddress((void**)&bnscale, g_bnscale);
    cudaGetSymbolAddress((void**)&bnshift, g_bnshift);
    cudaGetSymbolAddress((void**)&idegi, g_idegi);
    cudaGetSymbolAddress((void**)&idegc, g_idegc);
    cudaGetSymbolAddress((void**)&rpi, g_rpi);
    cudaGetSymbolAddress((void**)&rpc, g_rpc);
    cudaGetSymbolAddress((void**)&curi, g_curi);
    cudaGetSymbolAddress((void**)&curc, g_curc);
    cudaGetSymbolAddress((void**)&bsum, g_bsum);
    cudaGetSymbolAddress((void**)&ci, g_ci);
    cudaGetSymbolAddress((void**)&ccol, g_ccol);

    const int NB = cdiv(NN, 256);

    prep_w<<<cdiv(FDIM * 256, 256), 256>>>(Wgc[0], Wgat[0], nullptr, FDIM, wp);
    prep_c<<<256, 128>>>(Wgc[0], Wgat[0], nullptr, FDIM, cvec);
    init_zero<<<cdiv(NN, 256), 256>>>(iso, idegi, idegc, att);
    edge_deg<<<cdiv(EIN + ECN, 256), 256>>>(isrc, idst, cdst, iso, idegi, idegc);
    inv_both<<<cdiv(NN, 256), 256>>>(iso, idegi, isi);

    // CSR build (dual)
    scan1dual<<<NB, 256>>>(idegi, idegc, rpi, rpc, bsum, NN);
    scan2dual<<<1, 512>>>(bsum, NB);
    scan3dual<<<NB, 256>>>(rpi, rpc, bsum, curi, curc, NN);
    scatter_dual<<<cdiv(EIN + ECN, 256), 256>>>(isrc, idst, csrc, cdst, curi, curc, ci, ccol);

    const int Hs[3] = {4, 4, 1};
    for (int L = 0; L < 3; L++) {
        int K = (L == 0) ? FDIM : CC;
        int H = Hs[L];

        if (L > 0) {
            prep_w<<<cdiv(K * 256, 256), 256>>>(Wgc[L], Wgat[L], bnscale, K, wp);
            prep_c<<<256, 128>>>(Wgc[L], Wgat[L], bnshift, K, cvec);
        }
        zero_layer<<<cdiv(NN * 4, 256), 256>>>(el, er, bnsum, bnsq);
        gemm_dual_async<<<cdiv(NN, 128), 512>>>((L == 0) ? feat : z, wp, cvec, xw, f,
                                                iso, al[L], ar[L], el, er, NN, K, H);

        if (H == 4)
            gat_ms_alpha<4><<<2048, 128>>>(el, er, rpc, idegc, ccol, alpha, nullptr);
        else
            gat_ms_alpha<1><<<2048, 128>>>(el, er, rpc, idegc, ccol, alpha, att);

        if (L < 2)
            layer_fused<4, 1><<<2048, 128>>>(xw, f, alpha, isi, rpi, idegi, ci,
                                             rpc, idegc, ccol, bgc[L], bga[L],
                                             z, bnsum, bnsq);
        else
            layer_fused<1, 0><<<2048, 128>>>(xw, f, alpha, isi, rpi, idegi, ci,
                                             rpc, idegc, ccol, bgc[L], bga[L],
                                             z, bnsum, bnsq);

        bn_prep<<<1, 128>>>(bnsum, bnsq, gam[L], bet[L], bnscale, bnshift);
    }

    // ---- pooling (bn affine fused) ----
    fill_kernel<<<cdiv(GN * CC, 256), 256>>>(gsum, 0.f, GN * CC);
    fill_kernel<<<cdiv(GN, 256), 256>>>(gcnt, 0.f, GN);
    gcnt_kernel<<<cdiv(NN, 256), 256>>>(gid, gcnt);
    pool_kernel<<<cdiv(NN * CC, 256), 256>>>(z, bnscale, bnshift, att, gid, gsum);
    out_kernel<<<cdiv(GN * CC + NN, 256), 256>>>(gsum, gcnt, att, out);
}

// round 14
// speedup vs baseline: 1.3620x; 1.0262x over previous
#include <cuda_runtime.h>
#include <cuda_fp16.h>
#include <cstdint>

#define NN  100000
#define EIN 1600000
#define ECN 800000
#define GN  2000
#define FDIM 512
#define CC  128

// -------- scratch (device globals; no allocation) --------
__device__ __half g_xw[NN*CC];
__device__ __half g_f[NN*CC];
__device__ float g_z[NN*CC];
__device__ float g_el[NN*4];
__device__ float g_er[NN*4];
__device__ float g_alpha[ECN*4];
__device__ float g_iso[NN];
__device__ float g_isi[NN];
__device__ float g_att[NN];
__device__ float g_gsum[GN*CC];
__device__ float g_gcnt[GN];
__device__ float g_bnsum[2*CC];   // ping-pong by layer parity
__device__ float g_bnsq[2*CC];
__device__ __half g_wp[256*FDIM]; // transposed [n][k], fp16
__device__ float g_cvec[256];
// CSR scratch
__device__ int g_idegi[NN];
__device__ int g_idegc[NN];
__device__ int g_rpi[NN];
__device__ int g_rpc[NN];
__device__ int g_curi[NN];
__device__ int g_curc[NN];
__device__ int g_bsum[1024];
__device__ int g_ci[EIN];
__device__ int g_ccol[ECN];

__device__ __forceinline__ float leakyr(float x) { return x >= 0.f ? x : 0.2f * x; }

__device__ __forceinline__ void mma_f16(float* d, const uint32_t* a, const uint32_t* b) {
    asm volatile(
        "mma.sync.aligned.m16n8k16.row.col.f32.f16.f16.f32 "
        "{%0,%1,%2,%3}, {%4,%5,%6,%7}, {%8,%9}, {%0,%1,%2,%3};"
        : "+f"(d[0]), "+f"(d[1]), "+f"(d[2]), "+f"(d[3])
        : "r"(a[0]), "r"(a[1]), "r"(a[2]), "r"(a[3]), "r"(b[0]), "r"(b[1]));
}

__device__ __forceinline__ uint32_t packh2(float lo, float hi) {
    __half2 h = __floats2half2_rn(lo, hi);
    return *(uint32_t*)&h;
}

__device__ __forceinline__ void cp16(uint32_t dst, const void* src, int sz) {
    asm volatile("cp.async.cg.shared.global [%0], [%1], 16, %2;"
                 :: "r"(dst), "l"(src), "r"(sz) : "memory");
}

// -------- init: node arrays + pooling buffers --------
__global__ void init_zero(float* iso, int* idegi, int* idegc, float* att,
                          float* gsum, float* gcnt) {
    int i = blockIdx.x * blockDim.x + threadIdx.x;
    if (i < NN) { iso[i] = 0.f; idegi[i] = 0; idegc[i] = 0; att[i] = 0.f; }
    if (i < GN * CC) gsum[i] = 0.f;
    if (i < GN) gcnt[i] = 0.f;
}

// -------- degrees + graph-count in one pass --------
__global__ void edge_deg(const int* __restrict__ isrc, const int* __restrict__ idst,
                         const int* __restrict__ cdst, const int* __restrict__ gid,
                         float* iso, int* idegi, int* idegc, float* gcnt) {
    int t = blockIdx.x * blockDim.x + threadIdx.x;
    if (t < EIN) {
        atomicAdd(&iso[isrc[t]], 1.f);
        atomicAdd(&idegi[idst[t]], 1);
    } else if (t < EIN + ECN) {
        atomicAdd(&idegc[cdst[t - EIN]], 1);
    } else if (t < EIN + ECN + NN) {
        atomicAdd(&gcnt[gid[t - EIN - ECN]], 1.f);
    }
}

// -------- dual scan stage 1 (+ inv-sqrt degree finalize) --------
__global__ void scan1dual(const int* __restrict__ in1, const int* __restrict__ in2,
                          int* out1, int* out2, int* bsum,
                          float* iso, float* isi, int n) {
    __shared__ int sh1[256], sh2[256];
    int i = blockIdx.x * 256 + threadIdx.x;
    int v1 = (i < n) ? in1[i] : 0;
    int v2 = (i < n) ? in2[i] : 0;
    if (i < n) {
        isi[i] = rsqrtf(fmaxf((float)v1, 1.f));
        iso[i] = rsqrtf(fmaxf(iso[i], 1.f));
    }
    sh1[threadIdx.x] = v1; sh2[threadIdx.x] = v2;
    __syncthreads();
    for (int off = 1; off < 256; off <<= 1) {
        int t1 = (threadIdx.x >= off) ? sh1[threadIdx.x - off] : 0;
        int t2 = (threadIdx.x >= off) ? sh2[threadIdx.x - off] : 0;
        __syncthreads();
        sh1[threadIdx.x] += t1; sh2[threadIdx.x] += t2;
        __syncthreads();
    }
    if (i < n) { out1[i] = sh1[threadIdx.x] - v1; out2[i] = sh2[threadIdx.x] - v2; }
    if (threadIdx.x == 255) {
        bsum[blockIdx.x] = sh1[255];
        bsum[512 + blockIdx.x] = sh2[255];
    }
}
__global__ void scan2dual(int* bsum, int nb) {
    __shared__ int sh[512];
    int t = threadIdx.x;
    for (int a = 0; a < 2; a++) {
        int* bs = bsum + a * 512;
        int v = (t < nb) ? bs[t] : 0;
        sh[t] = v;
        __syncthreads();
        for (int off = 1; off < 512; off <<= 1) {
            int x = (t >= off) ? sh[t - off] : 0;
            __syncthreads();
            sh[t] += x;
            __syncthreads();
        }
        if (t < nb) bs[t] = sh[t] - v;
        __syncthreads();
    }
}
__global__ void scan3dual(int* out1, int* out2, const int* __restrict__ bsum,
                          int* cur1, int* cur2, int n) {
    int i = blockIdx.x * 256 + threadIdx.x;
    if (i >= n) return;
    int r1 = out1[i] + bsum[blockIdx.x];
    int r2 = out2[i] + bsum[512 + blockIdx.x];
    out1[i] = r1; out2[i] = r2;
    cur1[i] = r1; cur2[i] = r2;
}
__global__ void scatter_dual(const int* __restrict__ isrc, const int* __restrict__ idst,
                             const int* __restrict__ csrc, const int* __restrict__ cdst,
                             int* curi, int* curc, int* ci, int* ccol) {
    int t = blockIdx.x * blockDim.x + threadIdx.x;
    if (t < EIN) {
        int p = atomicAdd(&curi[idst[t]], 1);
        ci[p] = isrc[t];
    } else if (t < EIN + ECN) {
        int e = t - EIN;
        int p = atomicAdd(&curc[cdst[e]], 1);
        ccol[p] = csrc[e];
    }
}

// ===================================================================
// prep_all: weight fold (inline BN scale) + bias fold + zero el/er/bn
// blocks [0,K): Wp[j][k] = fp16(sc[k]*W[k][j])  (k = blockIdx, j = tid)
// blocks [K,K+256): cvec[j] = sum_k shift[k]*W[k][j]
// blocks [K+256, ...): zero el, er (NN*4) and bnsumC/bnsqC (CC)
// ===================================================================
__global__ __launch_bounds__(256) void prep_all(
    const float* __restrict__ Wgc, const float* __restrict__ Wgat,
    const float* __restrict__ gamP, const float* __restrict__ betP,
    const float* __restrict__ bnsumP, const float* __restrict__ bnsqP, int hasAff,
    int K, __half* __restrict__ Wp, float* __restrict__ cvec,
    float* __restrict__ el, float* __restrict__ er,
    float* __restrict__ bnsumC, float* __restrict__ bnsqC)
{
    int b = blockIdx.x;
    int t = threadIdx.x;
    if (b < K) {
        int k = b, j = t;
        float sc = 1.f;
        if (hasAff) {
            float mu = bnsumP[k] / (float)NN;
            float var = bnsqP[k] / (float)NN - mu * mu;
            sc = gamP[k] * rsqrtf(var + 1e-5f);
        }
        float w = (j < 128) ? Wgc[k * 128 + j] : Wgat[k * 128 + j - 128];
        Wp[(size_t)j * K + k] = __float2half(sc * w);
        return;
    }
    b -= K;
    if (b < 256) {
        __shared__ float sh[256];
        int j = b;
        float acc = 0.f;
        if (hasAff) {
            const float* W = (j < 128) ? (Wgc + j) : (Wgat + j - 128);
            for (int k = t; k < K; k += 256) {
                float mu = bnsumP[k] / (float)NN;
                float var = bnsqP[k] / (float)NN - mu * mu;
                float sck = gamP[k] * rsqrtf(var + 1e-5f);
                float shk = betP[k] - mu * sck;
                acc += shk * W[(size_t)k * 128];
            }
        }
        sh[t] = acc;
        __syncthreads();
        for (int off = 128; off; off >>= 1) {
            if (t < off) sh[t] += sh[t + off];
            __syncthreads();
        }
        if (t == 0) cvec[j] = sh[0];
        return;
    }
    b -= 256;
    int idx = b * 256 + t;
    if (idx < NN * 4) { el[idx] = 0.f; er[idx] = 0.f; }
    if (idx < CC) { bnsumC[idx] = 0.f; bnsqC[idx] = 0.f; }
}

// ===================================================================
// Dual-GEMM, fp16 m16n8k16 mma, fp32 accum, cp.async 3-stage, BK=16
// ===================================================================
__global__ __launch_bounds__(512, 1) void gemm_dual_async(
    const float* __restrict__ A, const __half* __restrict__ Wp,
    const float* __restrict__ cvec,
    __half* __restrict__ Ca, __half* __restrict__ Cb,
    const float* __restrict__ rowscale,
    const float* __restrict__ alv, const float* __restrict__ arv,
    float* __restrict__ el, float* __restrict__ er,
    int M, int K, int H)
{
    __shared__ __align__(16) float As[3][128 * 16];
    __shared__ __align__(16) __half Bs[3][256 * 16];

    const int tid = threadIdx.x;
    const int lane = tid & 31;
    const int wid = tid >> 5;
    const int wm = wid & 3;
    const int wn = wid >> 2;
    const int row0 = blockIdx.x * 128;
    const int iters = K >> 4;

    float acc[2][8][4];
#pragma unroll
    for (int i = 0; i < 2; i++)
#pragma unroll
        for (int j = 0; j < 8; j++)
#pragma unroll
            for (int q = 0; q < 4; q++) acc[i][j][q] = 0.f;

    const int ar_ = tid >> 2, akg = tid & 3;
    const int a_soff = ar_ * 16 + ((akg * 4) ^ (4 * (ar_ & 3)));
    const int a_sz = (row0 + ar_ < M) ? 16 : 0;
    const float* a_src_base = A + (size_t)(row0 + ar_) * K + akg * 4;

    const int bn = tid >> 1, bg = tid & 1;
    const int b_soff = bn * 16 + ((bg ^ (bn & 1)) << 3);
    const __half* b_src_base = Wp + (size_t)bn * K + bg * 8;

    auto loadTile = [&](int it) {
        int buf = it % 3;
        int k0 = it * 16;
        cp16((uint32_t)__cvta_generic_to_shared(&As[buf][a_soff]), a_src_base + k0, a_sz);
        cp16((uint32_t)__cvta_generic_to_shared(&Bs[buf][b_soff]), b_src_base + k0, 16);
        asm volatile("cp.async.commit_group;" ::: "memory");
    };

    loadTile(0);
    if (iters > 1) loadTile(1);
    else asm volatile("cp.async.commit_group;" ::: "memory");

    for (int it = 0; it < iters; ++it) {
        asm volatile("cp.async.wait_group 1;" ::: "memory");
        __syncthreads();
        if (it + 2 < iters) loadTile(it + 2);
        else asm volatile("cp.async.commit_group;" ::: "memory");

        const float* as = As[it % 3];
        const __half* bs = Bs[it % 3];

        uint32_t afr[2][4], bfr[8][2];
        const int c = (lane & 3) * 2;
#pragma unroll
        for (int i = 0; i < 2; i++) {
            int r = wm * 32 + i * 16 + (lane >> 2);
            int r2 = r + 8;
            int sw = 4 * (r & 3);
            int sw2 = 4 * (r2 & 3);
            float2 f00 = *(const float2*)&as[r * 16 + (c ^ sw)];
            float2 f10 = *(const float2*)&as[r2 * 16 + (c ^ sw2)];
            float2 f01 = *(const float2*)&as[r * 16 + ((c + 8) ^ sw)];
            float2 f11 = *(const float2*)&as[r2 * 16 + ((c + 8) ^ sw2)];
            afr[i][0] = packh2(f00.x, f00.y);
            afr[i][1] = packh2(f10.x, f10.y);
            afr[i][2] = packh2(f01.x, f01.y);
            afr[i][3] = packh2(f11.x, f11.y);
        }
#pragma unroll
        for (int j = 0; j < 8; j++) {
            int n = wn * 64 + j * 8 + (lane >> 2);
            const __half* brow = bs + n * 16;
            int g0 = (0 ^ (n & 1)) << 3;
            int g1 = (1 ^ (n & 1)) << 3;
            bfr[j][0] = *(const uint32_t*)&brow[g0 + c];
            bfr[j][1] = *(const uint32_t*)&brow[g1 + c];
        }
#pragma unroll
        for (int i = 0; i < 2; i++)
#pragma unroll
            for (int j = 0; j < 8; j++)
                mma_f16(acc[i][j], afr[i], bfr[j]);
    }

    // ---- store epilogue (fp16 outputs) ----
#pragma unroll
    for (int i = 0; i < 2; i++) {
        int r = row0 + wm * 32 + i * 16 + (lane >> 2);
#pragma unroll
        for (int j = 0; j < 8; j++) {
            int col = wn * 64 + j * 8 + (lane & 3) * 2;
            float c0 = __ldg(cvec + col), c1 = __ldg(cvec + col + 1);
            __half* dstm;
            int cc;
            bool isA = (col < 128);
            if (isA) { dstm = Ca; cc = col; }
            else     { dstm = Cb; cc = col - 128; }
            if (r < M) {
                float s = isA ? __ldg(rowscale + r) : 1.f;
                *(__half2*)(dstm + (size_t)r * 128 + cc) =
                    __floats2half2_rn((acc[i][j][0] + c0) * s, (acc[i][j][1] + c1) * s);
            }
            if (r + 8 < M) {
                float s = isA ? __ldg(rowscale + r + 8) : 1.f;
                *(__half2*)(dstm + (size_t)(r + 8) * 128 + cc) =
                    __floats2half2_rn((acc[i][j][2] + c0) * s, (acc[i][j][3] + c1) * s);
            }
        }
    }

    // ---- fused el/er from fp32 accumulators (wn >= 2) ----
    if (wn >= 2) {
        const int hmask = (H == 4) ? 1 : 0;
        float pel[4][2], per_[4][2];
#pragma unroll
        for (int rr = 0; rr < 4; rr++) { pel[rr][0] = pel[rr][1] = 0.f; per_[rr][0] = per_[rr][1] = 0.f; }
#pragma unroll
        for (int i = 0; i < 2; i++)
#pragma unroll
            for (int j = 0; j < 8; j++) {
                int col = wn * 64 + j * 8 + (lane & 3) * 2;
                int cf = col - 128;
                float a0 = __ldg(alv + cf), a1 = __ldg(alv + cf + 1);
                float b0 = __ldg(arv + cf), b1 = __ldg(arv + cf + 1);
                float c0 = __ldg(cvec + col), c1 = __ldg(cvec + col + 1);
                int hg = (j >> 2) & hmask;
                float f0 = acc[i][j][0] + c0, f1 = acc[i][j][1] + c1;
                float f2 = acc[i][j][2] + c0, f3 = acc[i][j][3] + c1;
                pel[i * 2 + 0][hg] += f0 * a0 + f1 * a1;
                per_[i * 2 + 0][hg] += f0 * b0 + f1 * b1;
                pel[i * 2 + 1][hg] += f2 * a0 + f3 * a1;
                per_[i * 2 + 1][hg] += f2 * b0 + f3 * b1;
            }
#pragma unroll
        for (int rr = 0; rr < 4; rr++)
#pragma unroll
            for (int hg = 0; hg < 2; hg++) {
                float v = pel[rr][hg];
                v += __shfl_xor_sync(0xffffffffu, v, 1);
                v += __shfl_xor_sync(0xffffffffu, v, 2);
                pel[rr][hg] = v;
                float w = per_[rr][hg];
                w += __shfl_xor_sync(0xffffffffu, w, 1);
                w += __shfl_xor_sync(0xffffffffu, w, 2);
                per_[rr][hg] = w;
            }
        if ((lane & 3) == 0) {
#pragma unroll
            for (int rr = 0; rr < 4; rr++) {
                int row = row0 + wm * 32 + (rr >> 1) * 16 + (lane >> 2) + (rr & 1) * 8;
                if (row < M) {
#pragma unroll
                    for (int hg = 0; hg < 2; hg++) {
                        if (hg > hmask) break;
                        int h = (H == 4) ? ((wn - 2) * 2 + hg) : 0;
                        atomicAdd(&el[(size_t)row * H + h], pel[rr][hg]);
                        atomicAdd(&er[(size_t)row * H + h], per_[rr][hg]);
                    }
                }
            }
        }
    }
}

// -------- per-node softmax: warp-per-node grid-stride, alpha in CSR order --------
template<int H>
__global__ __launch_bounds__(128) void gat_ms_alpha(
    const float* __restrict__ el, const float* __restrict__ er,
    const int* __restrict__ rpc, const int* __restrict__ degc,
    const int* __restrict__ ccol, float* __restrict__ alpha, float* att)
{
    const int lane = threadIdx.x & 31;
    const int warp = (blockIdx.x * blockDim.x + threadIdx.x) >> 5;
    const int nwarps = (gridDim.x * blockDim.x) >> 5;
    const float4* el4 = (const float4*)el;
    const float4* er4 = (const float4*)er;

    for (int n = warp; n < NN; n += nwarps) {
        int c0 = __ldg(rpc + n), deg = __ldg(degc + n);
        if (deg == 0) continue;
        int cend = c0 + deg;

        if (H == 4) {
            float4 ern = __ldg(er4 + n);
            float m0 = -1e30f, m1 = -1e30f, m2 = -1e30f, m3 = -1e30f;
            float s0 = 0.f, s1 = 0.f, s2 = 0.f, s3 = 0.f;
            for (int j = c0 + lane; j < cend; j += 32) {
                int sn = __ldg(ccol + j);
                float4 e4 = __ldg(el4 + sn);
                float e0 = leakyr(e4.x + ern.x), e1 = leakyr(e4.y + ern.y);
                float e2 = leakyr(e4.z + ern.z), e3 = leakyr(e4.w + ern.w);
                if (e0 > m0) { s0 *= __expf(m0 - e0); m0 = e0; } s0 += __expf(e0 - m0);
                if (e1 > m1) { s1 *= __expf(m1 - e1); m1 = e1; } s1 += __expf(e1 - m1);
                if (e2 > m2) { s2 *= __expf(m2 - e2); m2 = e2; } s2 += __expf(e2 - m2);
                if (e3 > m3) { s3 *= __expf(m3 - e3); m3 = e3; } s3 += __expf(e3 - m3);
            }
#pragma unroll
            for (int off = 16; off; off >>= 1) {
                float mo, so, mm;
                mo = __shfl_xor_sync(0xffffffffu, m0, off); so = __shfl_xor_sync(0xffffffffu, s0, off);
                mm = fmaxf(m0, mo); s0 = s0 * __expf(m0 - mm) + so * __expf(mo - mm); m0 = mm;
                mo = __shfl_xor_sync(0xffffffffu, m1, off); so = __shfl_xor_sync(0xffffffffu, s1, off);
                mm = fmaxf(m1, mo); s1 = s1 * __expf(m1 - mm) + so * __expf(mo - mm); m1 = mm;
                mo = __shfl_xor_sync(0xffffffffu, m2, off); so = __shfl_xor_sync(0xffffffffu, s2, off);
                mm = fmaxf(m2, mo); s2 = s2 * __expf(m2 - mm) + so * __expf(mo - mm); m2 = mm;
                mo = __shfl_xor_sync(0xffffffffu, m3, off); so = __shfl_xor_sync(0xffffffffu, s3, off);
                mm = fmaxf(m3, mo); s3 = s3 * __expf(m3 - mm) + so * __expf(mo - mm); m3 = mm;
            }
            float i0 = 1.f / s0, i1 = 1.f / s1, i2 = 1.f / s2, i3 = 1.f / s3;
            for (int j = c0 + lane; j < cend; j += 32) {
                int sn = __ldg(ccol + j);
                float4 e4 = __ldg(el4 + sn);
                float4 o;
                o.x = __expf(leakyr(e4.x + ern.x) - m0) * i0;
                o.y = __expf(leakyr(e4.y + ern.y) - m1) * i1;
                o.z = __expf(leakyr(e4.z + ern.z) - m2) * i2;
                o.w = __expf(leakyr(e4.w + ern.w) - m3) * i3;
                ((float4*)alpha)[j] = o;
            }
        } else {
            float ern = __ldg(er + n);
            float m = -1e30f, s = 0.f;
            for (int j = c0 + lane; j < cend; j += 32) {
                int sn = __ldg(ccol + j);
                float e = leakyr(__ldg(el + sn) + ern);
                if (e > m) { s *= __expf(m - e); m = e; }
                s += __expf(e - m);
            }
#pragma unroll
            for (int off = 16; off; off >>= 1) {
                float mo = __shfl_xor_sync(0xffffffffu, m, off);
                float so = __shfl_xor_sync(0xffffffffu, s, off);
                float mm = fmaxf(m, mo);
                s = s * __expf(m - mm) + so * __expf(mo - mm);
                m = mm;
            }
            float inv = 1.f / s;
            for (int j = c0 + lane; j < cend; j += 32) {
                int sn = __ldg(ccol + j);
                float e = leakyr(__ldg(el + sn) + ern);
                float a = __expf(e - m) * inv;
                alpha[j] = a;
                atomicAdd(&att[sn], a);
            }
        }
    }
}

// ===================================================================
// Fused layer — FROZEN structure (2048 x 128, scalar fp16 gather)
// ===================================================================
template<int H, int DO_LEAKY>
__global__ __launch_bounds__(128) void layer_fused(
    const __half* __restrict__ xw, const __half* __restrict__ f,
    const float* __restrict__ alpha, const float* __restrict__ isi,
    const int* __restrict__ rpi, const int* __restrict__ degi, const int* __restrict__ ci,
    const int* __restrict__ rpc, const int* __restrict__ degc, const int* __restrict__ ccol,
    const float* __restrict__ bgc, const float* __restrict__ bga,
    float* __restrict__ z, float* __restrict__ bnsum, float* __restrict__ bnsq)
{
    const int ch = threadIdx.x;
    const int h = (H == 1) ? 0 : (ch >> 5);
    const float bc = __ldg(bgc + ch) + __ldg(bga + ch);
    float ls = 0.f, lq = 0.f;

    for (int n = blockIdx.x; n < NN; n += gridDim.x) {
        float a = 0.f;
        int j = __ldg(rpi + n);
        int bend = j + __ldg(degi + n);
        for (; j + 4 <= bend; j += 4) {
            int s0 = __ldg(ci + j), s1 = __ldg(ci + j + 1);
            int s2 = __ldg(ci + j + 2), s3 = __ldg(ci + j + 3);
            float v0 = __half2float(__ldg(xw + (size_t)s0 * 128 + ch));
            float v1 = __half2float(__ldg(xw + (size_t)s1 * 128 + ch));
            float v2 = __half2float(__ldg(xw + (size_t)s2 * 128 + ch));
            float v3 = __half2float(__ldg(xw + (size_t)s3 * 128 + ch));
            a += (v0 + v1) + (v2 + v3);
        }
        for (; j < bend; j++)
            a += __half2float(__ldg(xw + (size_t)__ldg(ci + j) * 128 + ch));

        float g = 0.f;
        int k = __ldg(rpc + n);
        int cend = k + __ldg(degc + n);
        for (; k + 4 <= cend; k += 4) {
            int s0 = __ldg(ccol + k), s1 = __ldg(ccol + k + 1);
            int s2 = __ldg(ccol + k + 2), s3 = __ldg(ccol + k + 3);
            float a0 = __ldg(alpha + (size_t)(k + 0) * H + h);
            float a1 = __ldg(alpha + (size_t)(k + 1) * H + h);
            float a2 = __ldg(alpha + (size_t)(k + 2) * H + h);
            float a3 = __ldg(alpha + (size_t)(k + 3) * H + h);
            float v0 = __half2float(__ldg(f + (size_t)s0 * 128 + ch));
            float v1 = __half2float(__ldg(f + (size_t)s1 * 128 + ch));
            float v2 = __half2float(__ldg(f + (size_t)s2 * 128 + ch));
            float v3 = __half2float(__ldg(f + (size_t)s3 * 128 + ch));
            g += a0 * v0 + a1 * v1 + a2 * v2 + a3 * v3;
        }
        for (; k < cend; k++) {
            int s0 = __ldg(ccol + k);
            g += __ldg(alpha + (size_t)k * H + h) * __half2float(__ldg(f + (size_t)s0 * 128 + ch));
        }

        float v = a * __ldg(isi + n) + g + bc;
        if (DO_LEAKY) v = leakyr(v);
        z[(size_t)n * 128 + ch] = v;
        ls += v;
        lq += v * v;
    }
    atomicAdd(&bnsum[ch], ls);
    atomicAdd(&bnsq[ch], lq);
}

// -------- pooling: layer-3 BN computed inline from bn stats --------
__global__ void pool_kernel(const float* __restrict__ z,
                            const float* __restrict__ bnsum, const float* __restrict__ bnsq,
                            const float* __restrict__ gam, const float* __restrict__ bet,
                            const float* __restrict__ att,
                            const int* __restrict__ gid, float* gsum)
{
    int idx = blockIdx.x * blockDim.x + threadIdx.x;
    if (idx >= NN * 128) return;
    int n = idx >> 7, ch = idx & 127;
    float mu = __ldg(bnsum + ch) / (float)NN;
    float var = __ldg(bnsq + ch) / (float)NN - mu * mu;
    float sc = __ldg(gam + ch) * rsqrtf(var + 1e-5f);
    float sh = __ldg(bet + ch) - mu * sc;
    float v = z[idx] * sc + sh;
    atomicAdd(&gsum[gid[n] * 128 + ch], v * att[n]);
}
__global__ void out_kernel(const float* __restrict__ gsum, const float* __restrict__ gcnt,
                           const float* __restrict__ att, float* __restrict__ out)
{
    int i = blockIdx.x * blockDim.x + threadIdx.x;
    if (i < GN * 128) {
        out[i] = gsum[i] / fmaxf(gcnt[i >> 7], 1.f);
    } else if (i < GN * 128 + NN) {
        out[i] = att[i - GN * 128];
    }
}

static inline int cdiv(int a, int b) { return (a + b - 1) / b; }

extern "C" void kernel_launch(void* const* d_in, const int* in_sizes, int n_in,
                              void* d_out, int out_size)
{
    (void)in_sizes; (void)n_in; (void)out_size;
    const float* feat = (const float*)d_in[0];
    const int* isrc = (const int*)d_in[1];
    const int* idst = (const int*)d_in[2];
    const int* csrc = (const int*)d_in[3];
    const int* cdst = (const int*)d_in[4];
    const int* gid  = (const int*)d_in[5];
    const float* Wgc[3]  = {(const float*)d_in[6],  (const float*)d_in[12], (const float*)d_in[18]};
    const float* bgc[3]  = {(const float*)d_in[7],  (const float*)d_in[13], (const float*)d_in[19]};
    const float* Wgat[3] = {(const float*)d_in[8],  (const float*)d_in[14], (const float*)d_in[20]};
    const float* al[3]   = {(const float*)d_in[9],  (const float*)d_in[15], (const float*)d_in[21]};
    const float* ar[3]   = {(const float*)d_in[10], (const float*)d_in[16], (const float*)d_in[22]};
    const float* bga[3]  = {(const float*)d_in[11], (const float*)d_in[17], (const float*)d_in[23]};
    const float* gam[3]  = {(const float*)d_in[24], (const float*)d_in[26], (const float*)d_in[28]};
    const float* bet[3]  = {(const float*)d_in[25], (const float*)d_in[27], (const float*)d_in[29]};
    float* out = (float*)d_out;

    __half *xw, *f, *wp;
    float *z, *el, *er, *alpha, *cvec;
    float *iso, *isi, *att, *gsum, *gcnt, *bnsum, *bnsq;
    int *idegi, *idegc, *rpi, *rpc, *curi, *curc, *bsum, *ci, *ccol;
    cudaGetSymbolAddress((void**)&xw, g_xw);
    cudaGetSymbolAddress((void**)&f, g_f);
    cudaGetSymbolAddress((void**)&z, g_z);
    cudaGetSymbolAddress((void**)&el, g_el);
    cudaGetSymbolAddress((void**)&er, g_er);
    cudaGetSymbolAddress((void**)&alpha, g_alpha);
    cudaGetSymbolAddress((void**)&wp, g_wp);
    cudaGetSymbolAddress((void**)&cvec, g_cvec);
    cudaGetSymbolAddress((void**)&iso, g_iso);
    cudaGetSymbolAddress((void**)&isi, g_isi);
    cudaGetSymbolAddress((void**)&att, g_att);
    cudaGetSymbolAddress((void**)&gsum, g_gsum);
    cudaGetSymbolAddress((void**)&gcnt, g_gcnt);
    cudaGetSymbolAddress((void**)&bnsum, g_bnsum);
    cudaGetSymbolAddress((void**)&bnsq, g_bnsq);
    cudaGetSymbolAddress((void**)&idegi, g_idegi);
    cudaGetSymbolAddress((void**)&idegc, g_idegc);
    cudaGetSymbolAddress((void**)&rpi, g_rpi);
    cudaGetSymbolAddress((void**)&rpc, g_rpc);
    cudaGetSymbolAddress((void**)&curi, g_curi);
    cudaGetSymbolAddress((void**)&curc, g_curc);
    cudaGetSymbolAddress((void**)&bsum, g_bsum);
    cudaGetSymbolAddress((void**)&ci, g_ci);
    cudaGetSymbolAddress((void**)&ccol, g_ccol);

    const int NB = cdiv(NN, 256);
    const int ZB = cdiv(NN * 4, 256);   // zero-block count in prep_all

    // layer-0 prep (no deps) — folds zeroing of el/er/bn set 0
    prep_all<<<FDIM + 256 + ZB, 256>>>(Wgc[0], Wgat[0], nullptr, nullptr,
                                       nullptr, nullptr, 0, FDIM, wp, cvec,
                                       el, er, bnsum, bnsq);
    init_zero<<<cdiv(GN * CC, 256), 256>>>(iso, idegi, idegc, att, gsum, gcnt);
    edge_deg<<<cdiv(EIN + ECN + NN, 256), 256>>>(isrc, idst, cdst, gid, iso, idegi, idegc, gcnt);
    scan1dual<<<NB, 256>>>(idegi, idegc, rpi, rpc, bsum, iso, isi, NN);
    scan2dual<<<1, 512>>>(bsum, NB);
    scan3dual<<<NB, 256>>>(rpi, rpc, bsum, curi, curc, NN);
    scatter_dual<<<cdiv(EIN + ECN, 256), 256>>>(isrc, idst, csrc, cdst, curi, curc, ci, ccol);

    const int Hs[3] = {4, 4, 1};
    for (int L = 0; L < 3; L++) {
        int K = (L == 0) ? FDIM : CC;
        int H = Hs[L];
        int cur = (L & 1) * CC;
        int prev = ((L + 1) & 1) * CC;   // (L-1)&1 == (L+1)&1

        if (L > 0)
            prep_all<<<K + 256 + ZB, 256>>>(Wgc[L], Wgat[L], gam[L - 1], bet[L - 1],
                                            bnsum + prev, bnsq + prev, 1, K, wp, cvec,
                                            el, er, bnsum + cur, bnsq + cur);

        gemm_dual_async<<<cdiv(NN, 128), 512>>>((L == 0) ? feat : z, wp, cvec, xw, f,
                                                iso, al[L], ar[L], el, er, NN, K, H);

        if (H == 4)
            gat_ms_alpha<4><<<2048, 128>>>(el, er, rpc, idegc, ccol, alpha, nullptr);
        else
            gat_ms_alpha<1><<<2048, 128>>>(el, er, rpc, idegc, ccol, alpha, att);

        if (L < 2)
            layer_fused<4, 1><<<2048, 128>>>(xw, f, alpha, isi, rpi, idegi, ci,
                                             rpc, idegc, ccol, bgc[L], bga[L],
                                             z, bnsum + cur, bnsq + cur);
        else
            layer_fused<1, 0><<<2048, 128>>>(xw, f, alpha, isi, rpi, idegi, ci,
                                             rpc, idegc, ccol, bgc[L], bga[L],
                                             z, bnsum + cur, bnsq + cur);
    }

    // ---- pooling: layer-2 parity = set 0 ----
    pool_kernel<<<cdiv(NN * CC, 256), 256>>>(z, bnsum, bnsq, gam[2], bet[2], att, gid, gsum);
    out_kernel<<<cdiv(GN * CC + NN, 256), 256>>>(gsum, gcnt, att, out);
}

// round 15
// speedup vs baseline: 1.4408x; 1.0579x over previous
#include <cuda_runtime.h>
#include <cuda_fp16.h>
#include <cstdint>

#define NN  100000
#define EIN 1600000
#define ECN 800000
#define GN  2000
#define FDIM 512
#define CC  128

// -------- scratch (device globals; no allocation) --------
__device__ __half g_xw[NN*CC];
__device__ __half g_f[NN*CC];
__device__ float g_z[NN*CC];
__device__ float g_el[NN*4];
__device__ float g_er[NN*4];
__device__ float g_iso[NN];
__device__ float g_isi[NN];
__device__ float g_att[NN];
__device__ float g_gsum[GN*CC];
__device__ float g_gcnt[GN];
__device__ float g_bnsum[2*CC];   // ping-pong by layer parity
__device__ float g_bnsq[2*CC];
__device__ __half g_wp[256*FDIM]; // transposed [n][k], fp16
__device__ float g_cvec[256];
// CSR scratch
__device__ int g_idegi[NN];
__device__ int g_idegc[NN];
__device__ int g_rpi[NN];
__device__ int g_rpc[NN];
__device__ int g_curi[NN];
__device__ int g_curc[NN];
__device__ int g_bsum[1024];
__device__ int g_ci[EIN];
__device__ int g_ccol[ECN];

__device__ __forceinline__ float leakyr(float x) { return x >= 0.f ? x : 0.2f * x; }

__device__ __forceinline__ void mma_f16(float* d, const uint32_t* a, const uint32_t* b) {
    asm volatile(
        "mma.sync.aligned.m16n8k16.row.col.f32.f16.f16.f32 "
        "{%0,%1,%2,%3}, {%4,%5,%6,%7}, {%8,%9}, {%0,%1,%2,%3};"
        : "+f"(d[0]), "+f"(d[1]), "+f"(d[2]), "+f"(d[3])
        : "r"(a[0]), "r"(a[1]), "r"(a[2]), "r"(a[3]), "r"(b[0]), "r"(b[1]));
}

__device__ __forceinline__ uint32_t packh2(float lo, float hi) {
    __half2 h = __floats2half2_rn(lo, hi);
    return *(uint32_t*)&h;
}

__device__ __forceinline__ void cp16(uint32_t dst, const void* src, int sz) {
    asm volatile("cp.async.cg.shared.global [%0], [%1], 16, %2;"
                 :: "r"(dst), "l"(src), "r"(sz) : "memory");
}

// -------- init: node arrays + pooling buffers --------
__global__ void init_zero(float* iso, int* idegi, int* idegc, float* att,
                          float* gsum, float* gcnt) {
    int i = blockIdx.x * blockDim.x + threadIdx.x;
    if (i < NN) { iso[i] = 0.f; idegi[i] = 0; idegc[i] = 0; att[i] = 0.f; }
    if (i < GN * CC) gsum[i] = 0.f;
    if (i < GN) gcnt[i] = 0.f;
}

// -------- degrees + graph-count in one pass --------
__global__ void edge_deg(const int* __restrict__ isrc, const int* __restrict__ idst,
                         const int* __restrict__ cdst, const int* __restrict__ gid,
                         float* iso, int* idegi, int* idegc, float* gcnt) {
    int t = blockIdx.x * blockDim.x + threadIdx.x;
    if (t < EIN) {
        atomicAdd(&iso[isrc[t]], 1.f);
        atomicAdd(&idegi[idst[t]], 1);
    } else if (t < EIN + ECN) {
        atomicAdd(&idegc[cdst[t - EIN]], 1);
    } else if (t < EIN + ECN + NN) {
        atomicAdd(&gcnt[gid[t - EIN - ECN]], 1.f);
    }
}

// -------- dual scan stage 1 (+ inv-sqrt degree finalize) --------
__global__ void scan1dual(const int* __restrict__ in1, const int* __restrict__ in2,
                          int* out1, int* out2, int* bsum,
                          float* iso, float* isi, int n) {
    __shared__ int sh1[256], sh2[256];
    int i = blockIdx.x * 256 + threadIdx.x;
    int v1 = (i < n) ? in1[i] : 0;
    int v2 = (i < n) ? in2[i] : 0;
    if (i < n) {
        isi[i] = rsqrtf(fmaxf((float)v1, 1.f));
        iso[i] = rsqrtf(fmaxf(iso[i], 1.f));
    }
    sh1[threadIdx.x] = v1; sh2[threadIdx.x] = v2;
    __syncthreads();
    for (int off = 1; off < 256; off <<= 1) {
        int t1 = (threadIdx.x >= off) ? sh1[threadIdx.x - off] : 0;
        int t2 = (threadIdx.x >= off) ? sh2[threadIdx.x - off] : 0;
        __syncthreads();
        sh1[threadIdx.x] += t1; sh2[threadIdx.x] += t2;
        __syncthreads();
    }
    if (i < n) { out1[i] = sh1[threadIdx.x] - v1; out2[i] = sh2[threadIdx.x] - v2; }
    if (threadIdx.x == 255) {
        bsum[blockIdx.x] = sh1[255];
        bsum[512 + blockIdx.x] = sh2[255];
    }
}
__global__ void scan2dual(int* bsum, int nb) {
    __shared__ int sh[512];
    int t = threadIdx.x;
    for (int a = 0; a < 2; a++) {
        int* bs = bsum + a * 512;
        int v = (t < nb) ? bs[t] : 0;
        sh[t] = v;
        __syncthreads();
        for (int off = 1; off < 512; off <<= 1) {
            int x = (t >= off) ? sh[t - off] : 0;
            __syncthreads();
            sh[t] += x;
            __syncthreads();
        }
        if (t < nb) bs[t] = sh[t] - v;
        __syncthreads();
    }
}
__global__ void scan3dual(int* out1, int* out2, const int* __restrict__ bsum,
                          int* cur1, int* cur2, int n) {
    int i = blockIdx.x * 256 + threadIdx.x;
    if (i >= n) return;
    int r1 = out1[i] + bsum[blockIdx.x];
    int r2 = out2[i] + bsum[512 + blockIdx.x];
    out1[i] = r1; out2[i] = r2;
    cur1[i] = r1; cur2[i] = r2;
}
__global__ void scatter_dual(const int* __restrict__ isrc, const int* __restrict__ idst,
                             const int* __restrict__ csrc, const int* __restrict__ cdst,
                             int* curi, int* curc, int* ci, int* ccol) {
    int t = blockIdx.x * blockDim.x + threadIdx.x;
    if (t < EIN) {
        int p = atomicAdd(&curi[idst[t]], 1);
        ci[p] = isrc[t];
    } else if (t < EIN + ECN) {
        int e = t - EIN;
        int p = atomicAdd(&curc[cdst[e]], 1);
        ccol[p] = csrc[e];
    }
}

// ===================================================================
// prep_all: weight fold (inline BN scale) + bias fold + zero el/er/bn
// ===================================================================
__global__ __launch_bounds__(256) void prep_all(
    const float* __restrict__ Wgc, const float* __restrict__ Wgat,
    const float* __restrict__ gamP, const float* __restrict__ betP,
    const float* __restrict__ bnsumP, const float* __restrict__ bnsqP, int hasAff,
    int K, __half* __restrict__ Wp, float* __restrict__ cvec,
    float* __restrict__ el, float* __restrict__ er,
    float* __restrict__ bnsumC, float* __restrict__ bnsqC)
{
    int b = blockIdx.x;
    int t = threadIdx.x;
    if (b < K) {
        int k = b, j = t;
        float sc = 1.f;
        if (hasAff) {
            float mu = bnsumP[k] / (float)NN;
            float var = bnsqP[k] / (float)NN - mu * mu;
            sc = gamP[k] * rsqrtf(var + 1e-5f);
        }
        float w = (j < 128) ? Wgc[k * 128 + j] : Wgat[k * 128 + j - 128];
        Wp[(size_t)j * K + k] = __float2half(sc * w);
        return;
    }
    b -= K;
    if (b < 256) {
        __shared__ float sh[256];
        int j = b;
        float acc = 0.f;
        if (hasAff) {
            const float* W = (j < 128) ? (Wgc + j) : (Wgat + j - 128);
            for (int k = t; k < K; k += 256) {
                float mu = bnsumP[k] / (float)NN;
                float var = bnsqP[k] / (float)NN - mu * mu;
                float sck = gamP[k] * rsqrtf(var + 1e-5f);
                float shk = betP[k] - mu * sck;
                acc += shk * W[(size_t)k * 128];
            }
        }
        sh[t] = acc;
        __syncthreads();
        for (int off = 128; off; off >>= 1) {
            if (t < off) sh[t] += sh[t + off];
            __syncthreads();
        }
        if (t == 0) cvec[j] = sh[0];
        return;
    }
    b -= 256;
    int idx = b * 256 + t;
    if (idx < NN * 4) { el[idx] = 0.f; er[idx] = 0.f; }
    if (idx < CC) { bnsumC[idx] = 0.f; bnsqC[idx] = 0.f; }
}

// ===================================================================
// Dual-GEMM, fp16 m16n8k16 mma, fp32 accum, cp.async 3-stage, BK=16
// ===================================================================
__global__ __launch_bounds__(512, 1) void gemm_dual_async(
    const float* __restrict__ A, const __half* __restrict__ Wp,
    const float* __restrict__ cvec,
    __half* __restrict__ Ca, __half* __restrict__ Cb,
    const float* __restrict__ rowscale,
    const float* __restrict__ alv, const float* __restrict__ arv,
    float* __restrict__ el, float* __restrict__ er,
    int M, int K, int H)
{
    __shared__ __align__(16) float As[3][128 * 16];
    __shared__ __align__(16) __half Bs[3][256 * 16];

    const int tid = threadIdx.x;
    const int lane = tid & 31;
    const int wid = tid >> 5;
    const int wm = wid & 3;
    const int wn = wid >> 2;
    const int row0 = blockIdx.x * 128;
    const int iters = K >> 4;

    float acc[2][8][4];
#pragma unroll
    for (int i = 0; i < 2; i++)
#pragma unroll
        for (int j = 0; j < 8; j++)
#pragma unroll
            for (int q = 0; q < 4; q++) acc[i][j][q] = 0.f;

    const int ar_ = tid >> 2, akg = tid & 3;
    const int a_soff = ar_ * 16 + ((akg * 4) ^ (4 * (ar_ & 3)));
    const int a_sz = (row0 + ar_ < M) ? 16 : 0;
    const float* a_src_base = A + (size_t)(row0 + ar_) * K + akg * 4;

    const int bn = tid >> 1, bg = tid & 1;
    const int b_soff = bn * 16 + ((bg ^ (bn & 1)) << 3);
    const __half* b_src_base = Wp + (size_t)bn * K + bg * 8;

    auto loadTile = [&](int it) {
        int buf = it % 3;
        int k0 = it * 16;
        cp16((uint32_t)__cvta_generic_to_shared(&As[buf][a_soff]), a_src_base + k0, a_sz);
        cp16((uint32_t)__cvta_generic_to_shared(&Bs[buf][b_soff]), b_src_base + k0, 16);
        asm volatile("cp.async.commit_group;" ::: "memory");
    };

    loadTile(0);
    if (iters > 1) loadTile(1);
    else asm volatile("cp.async.commit_group;" ::: "memory");

    for (int it = 0; it < iters; ++it) {
        asm volatile("cp.async.wait_group 1;" ::: "memory");
        __syncthreads();
        if (it + 2 < iters) loadTile(it + 2);
        else asm volatile("cp.async.commit_group;" ::: "memory");

        const float* as = As[it % 3];
        const __half* bs = Bs[it % 3];

        uint32_t afr[2][4], bfr[8][2];
        const int c = (lane & 3) * 2;
#pragma unroll
        for (int i = 0; i < 2; i++) {
            int r = wm * 32 + i * 16 + (lane >> 2);
            int r2 = r + 8;
            int sw = 4 * (r & 3);
            int sw2 = 4 * (r2 & 3);
            float2 f00 = *(const float2*)&as[r * 16 + (c ^ sw)];
            float2 f10 = *(const float2*)&as[r2 * 16 + (c ^ sw2)];
            float2 f01 = *(const float2*)&as[r * 16 + ((c + 8) ^ sw)];
            float2 f11 = *(const float2*)&as[r2 * 16 + ((c + 8) ^ sw2)];
            afr[i][0] = packh2(f00.x, f00.y);
            afr[i][1] = packh2(f10.x, f10.y);
            afr[i][2] = packh2(f01.x, f01.y);
            afr[i][3] = packh2(f11.x, f11.y);
        }
#pragma unroll
        for (int j = 0; j < 8; j++) {
            int n = wn * 64 + j * 8 + (lane >> 2);
            const __half* brow = bs + n * 16;
            int g0 = (0 ^ (n & 1)) << 3;
            int g1 = (1 ^ (n & 1)) << 3;
            bfr[j][0] = *(const uint32_t*)&brow[g0 + c];
            bfr[j][1] = *(const uint32_t*)&brow[g1 + c];
        }
#pragma unroll
        for (int i = 0; i < 2; i++)
#pragma unroll
            for (int j = 0; j < 8; j++)
                mma_f16(acc[i][j], afr[i], bfr[j]);
    }

    // ---- store epilogue (fp16 outputs) ----
#pragma unroll
    for (int i = 0; i < 2; i++) {
        int r = row0 + wm * 32 + i * 16 + (lane >> 2);
#pragma unroll
        for (int j = 0; j < 8; j++) {
            int col = wn * 64 + j * 8 + (lane & 3) * 2;
            float c0 = __ldg(cvec + col), c1 = __ldg(cvec + col + 1);
            __half* dstm;
            int cc;
            bool isA = (col < 128);
            if (isA) { dstm = Ca; cc = col; }
            else     { dstm = Cb; cc = col - 128; }
            if (r < M) {
                float s = isA ? __ldg(rowscale + r) : 1.f;
                *(__half2*)(dstm + (size_t)r * 128 + cc) =
                    __floats2half2_rn((acc[i][j][0] + c0) * s, (acc[i][j][1] + c1) * s);
            }
            if (r + 8 < M) {
                float s = isA ? __ldg(rowscale + r + 8) : 1.f;
                *(__half2*)(dstm + (size_t)(r + 8) * 128 + cc) =
                    __floats2half2_rn((acc[i][j][2] + c0) * s, (acc[i][j][3] + c1) * s);
            }
        }
    }

    // ---- fused el/er from fp32 accumulators (wn >= 2) ----
    if (wn >= 2) {
        const int hmask = (H == 4) ? 1 : 0;
        float pel[4][2], per_[4][2];
#pragma unroll
        for (int rr = 0; rr < 4; rr++) { pel[rr][0] = pel[rr][1] = 0.f; per_[rr][0] = per_[rr][1] = 0.f; }
#pragma unroll
        for (int i = 0; i < 2; i++)
#pragma unroll
            for (int j = 0; j < 8; j++) {
                int col = wn * 64 + j * 8 + (lane & 3) * 2;
                int cf = col - 128;
                float a0 = __ldg(alv + cf), a1 = __ldg(alv + cf + 1);
                float b0 = __ldg(arv + cf), b1 = __ldg(arv + cf + 1);
                float c0 = __ldg(cvec + col), c1 = __ldg(cvec + col + 1);
                int hg = (j >> 2) & hmask;
                float f0 = acc[i][j][0] + c0, f1 = acc[i][j][1] + c1;
                float f2 = acc[i][j][2] + c0, f3 = acc[i][j][3] + c1;
                pel[i * 2 + 0][hg] += f0 * a0 + f1 * a1;
                per_[i * 2 + 0][hg] += f0 * b0 + f1 * b1;
                pel[i * 2 + 1][hg] += f2 * a0 + f3 * a1;
                per_[i * 2 + 1][hg] += f2 * b0 + f3 * b1;
            }
#pragma unroll
        for (int rr = 0; rr < 4; rr++)
#pragma unroll
            for (int hg = 0; hg < 2; hg++) {
                float v = pel[rr][hg];
                v += __shfl_xor_sync(0xffffffffu, v, 1);
                v += __shfl_xor_sync(0xffffffffu, v, 2);
                pel[rr][hg] = v;
                float w = per_[rr][hg];
                w += __shfl_xor_sync(0xffffffffu, w, 1);
                w += __shfl_xor_sync(0xffffffffu, w, 2);
                per_[rr][hg] = w;
            }
        if ((lane & 3) == 0) {
#pragma unroll
            for (int rr = 0; rr < 4; rr++) {
                int row = row0 + wm * 32 + (rr >> 1) * 16 + (lane >> 2) + (rr & 1) * 8;
                if (row < M) {
#pragma unroll
                    for (int hg = 0; hg < 2; hg++) {
                        if (hg > hmask) break;
                        int h = (H == 4) ? ((wn - 2) * 2 + hg) : 0;
                        atomicAdd(&el[(size_t)row * H + h], pel[rr][hg]);
                        atomicAdd(&er[(size_t)row * H + h], per_[rr][hg]);
                    }
                }
            }
        }
    }
}

// ===================================================================
// Fused layer: per-warp softmax prologue (register alpha for deg<=32)
// + FROZEN gather structure (2048 x 128, scalar fp16 loads)
// ===================================================================
template<int H, int DO_LEAKY, int DO_ATT>
__global__ __launch_bounds__(128) void layer_fused(
    const __half* __restrict__ xw, const __half* __restrict__ f,
    const float* __restrict__ el, const float* __restrict__ er,
    const float* __restrict__ isi,
    const int* __restrict__ rpi, const int* __restrict__ degi, const int* __restrict__ ci,
    const int* __restrict__ rpc, const int* __restrict__ degc, const int* __restrict__ ccol,
    const float* __restrict__ bgc, const float* __restrict__ bga,
    float* __restrict__ z, float* __restrict__ bnsum, float* __restrict__ bnsq,
    float* __restrict__ att)
{
    const int ch = threadIdx.x;
    const int lane = ch & 31;
    const int wid = ch >> 5;
    const int hh = (H == 1) ? 0 : wid;
    const float bc = __ldg(bgc + ch) + __ldg(bga + ch);
    float ls = 0.f, lq = 0.f;

    for (int n = blockIdx.x; n < NN; n += gridDim.x) {
        // ---- GraphConv gather (frozen) ----
        float a = 0.f;
        int j = __ldg(rpi + n);
        int bend = j + __ldg(degi + n);
        for (; j + 4 <= bend; j += 4) {
            int s0 = __ldg(ci + j), s1 = __ldg(ci + j + 1);
            int s2 = __ldg(ci + j + 2), s3 = __ldg(ci + j + 3);
            float v0 = __half2float(__ldg(xw + (size_t)s0 * 128 + ch));
            float v1 = __half2float(__ldg(xw + (size_t)s1 * 128 + ch));
            float v2 = __half2float(__ldg(xw + (size_t)s2 * 128 + ch));
            float v3 = __half2float(__ldg(xw + (size_t)s3 * 128 + ch));
            a += (v0 + v1) + (v2 + v3);
        }
        for (; j < bend; j++)
            a += __half2float(__ldg(xw + (size_t)__ldg(ci + j) * 128 + ch));

        // ---- GAT: warp-local softmax + shfl-broadcast gather ----
        float g = 0.f;
        int c0 = __ldg(rpc + n), deg = __ldg(degc + n);
        if (deg > 0) {
            float ern = __ldg(er + (size_t)n * H + hh);
            if (deg <= 32) {
                int sn = 0;
                float e = -1e30f;
                bool valid = (lane < deg);
                if (valid) {
                    sn = __ldg(ccol + c0 + lane);
                    e = leakyr(__ldg(el + (size_t)sn * H + hh) + ern);
                }
                float m = e;
#pragma unroll
                for (int off = 16; off; off >>= 1)
                    m = fmaxf(m, __shfl_xor_sync(0xffffffffu, m, off));
                float ex = valid ? __expf(e - m) : 0.f;
                float s = ex;
#pragma unroll
                for (int off = 16; off; off >>= 1)
                    s += __shfl_xor_sync(0xffffffffu, s, off);
                float aj = ex / s;
                if (DO_ATT && wid == 0 && valid) atomicAdd(&att[sn], aj);
                int kk = 0;
                for (; kk + 4 <= deg; kk += 4) {
                    int s0 = __shfl_sync(0xffffffffu, sn, kk);
                    int s1 = __shfl_sync(0xffffffffu, sn, kk + 1);
                    int s2 = __shfl_sync(0xffffffffu, sn, kk + 2);
                    int s3 = __shfl_sync(0xffffffffu, sn, kk + 3);
                    float a0 = __shfl_sync(0xffffffffu, aj, kk);
                    float a1 = __shfl_sync(0xffffffffu, aj, kk + 1);
                    float a2 = __shfl_sync(0xffffffffu, aj, kk + 2);
                    float a3 = __shfl_sync(0xffffffffu, aj, kk + 3);
                    float v0 = __half2float(__ldg(f + (size_t)s0 * 128 + ch));
                    float v1 = __half2float(__ldg(f + (size_t)s1 * 128 + ch));
                    float v2 = __half2float(__ldg(f + (size_t)s2 * 128 + ch));
                    float v3 = __half2float(__ldg(f + (size_t)s3 * 128 + ch));
                    g += a0 * v0 + a1 * v1 + a2 * v2 + a3 * v3;
                }
                for (; kk < deg; kk++) {
                    int s0 = __shfl_sync(0xffffffffu, sn, kk);
                    float a0 = __shfl_sync(0xffffffffu, aj, kk);
                    g += a0 * __half2float(__ldg(f + (size_t)s0 * 128 + ch));
                }
            } else {
                int cend = c0 + deg;
                float m = -1e30f, s = 0.f;
                for (int jj = c0 + lane; jj < cend; jj += 32) {
                    int sn = __ldg(ccol + jj);
                    float e = leakyr(__ldg(el + (size_t)sn * H + hh) + ern);
                    if (e > m) { s *= __expf(m - e); m = e; }
                    s += __expf(e - m);
                }
#pragma unroll
                for (int off = 16; off; off >>= 1) {
                    float mo = __shfl_xor_sync(0xffffffffu, m, off);
                    float so = __shfl_xor_sync(0xffffffffu, s, off);
                    float mm = fmaxf(m, mo);
                    s = s * __expf(m - mm) + so * __expf(mo - mm);
                    m = mm;
                }
                float inv = 1.f / s;
                for (int j0 = c0; j0 < cend; j0 += 32) {
                    int cnt = min(32, cend - j0);
                    int sn = 0;
                    float aj = 0.f;
                    if (lane < cnt) {
                        sn = __ldg(ccol + j0 + lane);
                        float e = leakyr(__ldg(el + (size_t)sn * H + hh) + ern);
                        aj = __expf(e - m) * inv;
                        if (DO_ATT && wid == 0) atomicAdd(&att[sn], aj);
                    }
                    for (int kk = 0; kk < cnt; kk++) {
                        int s0 = __shfl_sync(0xffffffffu, sn, kk);
                        float a0 = __shfl_sync(0xffffffffu, aj, kk);
                        g += a0 * __half2float(__ldg(f + (size_t)s0 * 128 + ch));
                    }
                }
            }
        }

        float v = a * __ldg(isi + n) + g + bc;
        if (DO_LEAKY) v = leakyr(v);
        z[(size_t)n * 128 + ch] = v;
        ls += v;
        lq += v * v;
    }
    atomicAdd(&bnsum[ch], ls);
    atomicAdd(&bnsq[ch], lq);
}

// -------- pooling: layer-3 BN computed inline from bn stats --------
__global__ void pool_kernel(const float* __restrict__ z,
                            const float* __restrict__ bnsum, const float* __restrict__ bnsq,
                            const float* __restrict__ gam, const float* __restrict__ bet,
                            const float* __restrict__ att,
                            const int* __restrict__ gid, float* gsum)
{
    int idx = blockIdx.x * blockDim.x + threadIdx.x;
    if (idx >= NN * 128) return;
    int n = idx >> 7, ch = idx & 127;
    float mu = __ldg(bnsum + ch) / (float)NN;
    float var = __ldg(bnsq + ch) / (float)NN - mu * mu;
    float sc = __ldg(gam + ch) * rsqrtf(var + 1e-5f);
    float sh = __ldg(bet + ch) - mu * sc;
    float v = z[idx] * sc + sh;
    atomicAdd(&gsum[gid[n] * 128 + ch], v * att[n]);
}
__global__ void out_kernel(const float* __restrict__ gsum, const float* __restrict__ gcnt,
                           const float* __restrict__ att, float* __restrict__ out)
{
    int i = blockIdx.x * blockDim.x + threadIdx.x;
    if (i < GN * 128) {
        out[i] = gsum[i] / fmaxf(gcnt[i >> 7], 1.f);
    } else if (i < GN * 128 + NN) {
        out[i] = att[i - GN * 128];
    }
}

static inline int cdiv(int a, int b) { return (a + b - 1) / b; }

extern "C" void kernel_launch(void* const* d_in, const int* in_sizes, int n_in,
                              void* d_out, int out_size)
{
    (void)in_sizes; (void)n_in; (void)out_size;
    const float* feat = (const float*)d_in[0];
    const int* isrc = (const int*)d_in[1];
    const int* idst = (const int*)d_in[2];
    const int* csrc = (const int*)d_in[3];
    const int* cdst = (const int*)d_in[4];
    const int* gid  = (const int*)d_in[5];
    const float* Wgc[3]  = {(const float*)d_in[6],  (const float*)d_in[12], (const float*)d_in[18]};
    const float* bgc[3]  = {(const float*)d_in[7],  (const float*)d_in[13], (const float*)d_in[19]};
    const float* Wgat[3] = {(const float*)d_in[8],  (const float*)d_in[14], (const float*)d_in[20]};
    const float* al[3]   = {(const float*)d_in[9],  (const float*)d_in[15], (const float*)d_in[21]};
    const float* ar[3]   = {(const float*)d_in[10], (const float*)d_in[16], (const float*)d_in[22]};
    const float* bga[3]  = {(const float*)d_in[11], (const float*)d_in[17], (const float*)d_in[23]};
    const float* gam[3]  = {(const float*)d_in[24], (const float*)d_in[26], (const float*)d_in[28]};
    const float* bet[3]  = {(const float*)d_in[25], (const float*)d_in[27], (const float*)d_in[29]};
    float* out = (float*)d_out;

    __half *xw, *f, *wp;
    float *z, *el, *er, *cvec;
    float *iso, *isi, *att, *gsum, *gcnt, *bnsum, *bnsq;
    int *idegi, *idegc, *rpi, *rpc, *curi, *curc, *bsum, *ci, *ccol;
    cudaGetSymbolAddress((void**)&xw, g_xw);
    cudaGetSymbolAddress((void**)&f, g_f);
    cudaGetSymbolAddress((void**)&z, g_z);
    cudaGetSymbolAddress((void**)&el, g_el);
    cudaGetSymbolAddress((void**)&er, g_er);
    cudaGetSymbolAddress((void**)&wp, g_wp);
    cudaGetSymbolAddress((void**)&cvec, g_cvec);
    cudaGetSymbolAddress((void**)&iso, g_iso);
    cudaGetSymbolAddress((void**)&isi, g_isi);
    cudaGetSymbolAddress((void**)&att, g_att);
    cudaGetSymbolAddress((void**)&gsum, g_gsum);
    cudaGetSymbolAddress((void**)&gcnt, g_gcnt);
    cudaGetSymbolAddress((void**)&bnsum, g_bnsum);
    cudaGetSymbolAddress((void**)&bnsq, g_bnsq);
    cudaGetSymbolAddress((void**)&idegi, g_idegi);
    cudaGetSymbolAddress((void**)&idegc, g_idegc);
    cudaGetSymbolAddress((void**)&rpi, g_rpi);
    cudaGetSymbolAddress((void**)&rpc, g_rpc);
    cudaGetSymbolAddress((void**)&curi, g_curi);
    cudaGetSymbolAddress((void**)&curc, g_curc);
    cudaGetSymbolAddress((void**)&bsum, g_bsum);
    cudaGetSymbolAddress((void**)&ci, g_ci);
    cudaGetSymbolAddress((void**)&ccol, g_ccol);

    const int NB = cdiv(NN, 256);
    const int ZB = cdiv(NN * 4, 256);

    prep_all<<<FDIM + 256 + ZB, 256>>>(Wgc[0], Wgat[0], nullptr, nullptr,
                                       nullptr, nullptr, 0, FDIM, wp, cvec,
                                       el, er, bnsum, bnsq);
    init_zero<<<cdiv(GN * CC, 256), 256>>>(iso, idegi, idegc, att, gsum, gcnt);
    edge_deg<<<cdiv(EIN + ECN + NN, 256), 256>>>(isrc, idst, cdst, gid, iso, idegi, idegc, gcnt);
    scan1dual<<<NB, 256>>>(idegi, idegc, rpi, rpc, bsum, iso, isi, NN);
    scan2dual<<<1, 512>>>(bsum, NB);
    scan3dual<<<NB, 256>>>(rpi, rpc, bsum, curi, curc, NN);
    scatter_dual<<<cdiv(EIN + ECN, 256), 256>>>(isrc, idst, csrc, cdst, curi, curc, ci, ccol);

    const int Hs[3] = {4, 4, 1};
    for (int L = 0; L < 3; L++) {
        int K = (L == 0) ? FDIM : CC;
        int H = Hs[L];
        int cur = (L & 1) * CC;
        int prev = ((L + 1) & 1) * CC;

        if (L > 0)
            prep_all<<<K + 256 + ZB, 256>>>(Wgc[L], Wgat[L], gam[L - 1], bet[L - 1],
                                            bnsum + prev, bnsq + prev, 1, K, wp, cvec,
                                            el, er, bnsum + cur, bnsq + cur);

        gemm_dual_async<<<cdiv(NN, 128), 512>>>((L == 0) ? feat : z, wp, cvec, xw, f,
                                                iso, al[L], ar[L], el, er, NN, K, H);

        if (L < 2)
            layer_fused<4, 1, 0><<<2048, 128>>>(xw, f, el, er, isi, rpi, idegi, ci,
                                                rpc, idegc, ccol, bgc[L], bga[L],
                                                z, bnsum + cur, bnsq + cur, att);
        else
            layer_fused<1, 0, 1><<<2048, 128>>>(xw, f, el, er, isi, rpi, idegi, ci,
                                                rpc, idegc, ccol, bgc[L], bga[L],
                                                z, bnsum + cur, bnsq + cur, att);
    }

    // ---- pooling: layer-2 parity = set 0 ----
    pool_kernel<<<cdiv(NN * CC, 256), 256>>>(z, bnsum, bnsq, gam[2], bet[2], att, gid, gsum);
    out_kernel<<<cdiv(GN * CC + NN, 256), 256>>>(gsum, gcnt, att, out);
}

// round 16
// speedup vs baseline: 1.4572x; 1.0113x over previous
#include <cuda_runtime.h>
#include <cuda_fp16.h>
#include <cstdint>

#define NN  100000
#define EIN 1600000
#define ECN 800000
#define GN  2000
#define FDIM 512
#define CC  128

// -------- scratch (device globals; no allocation) --------
__device__ __half g_xw[NN*CC];
__device__ __half g_f[NN*CC];
__device__ float g_z[NN*CC];
__device__ float g_el[NN*4];
__device__ float g_er[NN*4];
__device__ float g_iso[NN];
__device__ float g_isi[NN];
__device__ float g_att[NN];
__device__ float g_gsum[GN*CC];
__device__ float g_gcnt[GN];
__device__ float g_bnsum[2*CC];
__device__ float g_bnsq[2*CC];
__device__ __half g_wp[256*FDIM];
__device__ float g_cvec[256];
// CSR scratch
__device__ int g_idegi[NN];
__device__ int g_idegc[NN];
__device__ int g_rpi[NN];
__device__ int g_rpc[NN];
__device__ int g_curi[NN];
__device__ int g_curc[NN];
__device__ int g_bsum[1024];
__device__ int g_ci[EIN];
__device__ int g_ccol[ECN];

__device__ __forceinline__ float leakyr(float x) { return x >= 0.f ? x : 0.2f * x; }

__device__ __forceinline__ void mma_f16(float* d, const uint32_t* a, const uint32_t* b) {
    asm volatile(
        "mma.sync.aligned.m16n8k16.row.col.f32.f16.f16.f32 "
        "{%0,%1,%2,%3}, {%4,%5,%6,%7}, {%8,%9}, {%0,%1,%2,%3};"
        : "+f"(d[0]), "+f"(d[1]), "+f"(d[2]), "+f"(d[3])
        : "r"(a[0]), "r"(a[1]), "r"(a[2]), "r"(a[3]), "r"(b[0]), "r"(b[1]));
}

__device__ __forceinline__ uint32_t packh2(float lo, float hi) {
    __half2 h = __floats2half2_rn(lo, hi);
    return *(uint32_t*)&h;
}

__device__ __forceinline__ void cp16(uint32_t dst, const void* src, int sz) {
    asm volatile("cp.async.cg.shared.global [%0], [%1], 16, %2;"
                 :: "r"(dst), "l"(src), "r"(sz) : "memory");
}

// -------- degrees + graph-count in one pass --------
__global__ void edge_deg(const int* __restrict__ isrc, const int* __restrict__ idst,
                         const int* __restrict__ cdst, const int* __restrict__ gid,
                         float* iso, int* idegi, int* idegc, float* gcnt) {
    int t = blockIdx.x * blockDim.x + threadIdx.x;
    if (t < EIN) {
        atomicAdd(&iso[isrc[t]], 1.f);
        atomicAdd(&idegi[idst[t]], 1);
    } else if (t < EIN + ECN) {
        atomicAdd(&idegc[cdst[t - EIN]], 1);
    } else if (t < EIN + ECN + NN) {
        atomicAdd(&gcnt[gid[t - EIN - ECN]], 1.f);
    }
}

// -------- dual scan stage 1 (+ inv-sqrt degree finalize) --------
__global__ void scan1dual(const int* __restrict__ in1, const int* __restrict__ in2,
                          int* out1, int* out2, int* bsum,
                          float* iso, float* isi, int n) {
    __shared__ int sh1[256], sh2[256];
    int i = blockIdx.x * 256 + threadIdx.x;
    int v1 = (i < n) ? in1[i] : 0;
    int v2 = (i < n) ? in2[i] : 0;
    if (i < n) {
        isi[i] = rsqrtf(fmaxf((float)v1, 1.f));
        iso[i] = rsqrtf(fmaxf(iso[i], 1.f));
    }
    sh1[threadIdx.x] = v1; sh2[threadIdx.x] = v2;
    __syncthreads();
    for (int off = 1; off < 256; off <<= 1) {
        int t1 = (threadIdx.x >= off) ? sh1[threadIdx.x - off] : 0;
        int t2 = (threadIdx.x >= off) ? sh2[threadIdx.x - off] : 0;
        __syncthreads();
        sh1[threadIdx.x] += t1; sh2[threadIdx.x] += t2;
        __syncthreads();
    }
    if (i < n) { out1[i] = sh1[threadIdx.x] - v1; out2[i] = sh2[threadIdx.x] - v2; }
    if (threadIdx.x == 255) {
        bsum[blockIdx.x] = sh1[255];
        bsum[512 + blockIdx.x] = sh2[255];
    }
}
__global__ void scan2dual(int* bsum, int nb) {
    __shared__ int sh[512];
    int t = threadIdx.x;
    for (int a = 0; a < 2; a++) {
        int* bs = bsum + a * 512;
        int v = (t < nb) ? bs[t] : 0;
        sh[t] = v;
        __syncthreads();
        for (int off = 1; off < 512; off <<= 1) {
            int x = (t >= off) ? sh[t - off] : 0;
            __syncthreads();
            sh[t] += x;
            __syncthreads();
        }
        if (t < nb) bs[t] = sh[t] - v;
        __syncthreads();
    }
}
__global__ void scan3dual(int* out1, int* out2, const int* __restrict__ bsum,
                          int* cur1, int* cur2, int n) {
    int i = blockIdx.x * 256 + threadIdx.x;
    if (i >= n) return;
    int r1 = out1[i] + bsum[blockIdx.x];
    int r2 = out2[i] + bsum[512 + blockIdx.x];
    out1[i] = r1; out2[i] = r2;
    cur1[i] = r1; cur2[i] = r2;
}
__global__ void scatter_dual(const int* __restrict__ isrc, const int* __restrict__ idst,
                             const int* __restrict__ csrc, const int* __restrict__ cdst,
                             int* curi, int* curc, int* ci, int* ccol) {
    int t = blockIdx.x * blockDim.x + threadIdx.x;
    if (t < EIN) {
        int p = atomicAdd(&curi[idst[t]], 1);
        ci[p] = isrc[t];
    } else if (t < EIN + ECN) {
        int e = t - EIN;
        int p = atomicAdd(&curc[cdst[e]], 1);
        ccol[p] = csrc[e];
    }
}

// ===================================================================
// prep_all: weight fold + bias fold + zero el/er/bn (+ one-time init)
// ===================================================================
__global__ __launch_bounds__(256) void prep_all(
    const float* __restrict__ Wgc, const float* __restrict__ Wgat,
    const float* __restrict__ gamP, const float* __restrict__ betP,
    const float* __restrict__ bnsumP, const float* __restrict__ bnsqP, int hasAff,
    int K, __half* __restrict__ Wp, float* __restrict__ cvec,
    float* __restrict__ el, float* __restrict__ er,
    float* __restrict__ bnsumC, float* __restrict__ bnsqC,
    int initAll, float* iso, int* idegi, int* idegc, float* att,
    float* gsum, float* gcnt)
{
    int b = blockIdx.x;
    int t = threadIdx.x;
    if (b < K) {
        int k = b, j = t;
        float sc = 1.f;
        if (hasAff) {
            float mu = bnsumP[k] / (float)NN;
            float var = bnsqP[k] / (float)NN - mu * mu;
            sc = gamP[k] * rsqrtf(var + 1e-5f);
        }
        float w = (j < 128) ? Wgc[k * 128 + j] : Wgat[k * 128 + j - 128];
        Wp[(size_t)j * K + k] = __float2half(sc * w);
        return;
    }
    b -= K;
    if (b < 256) {
        __shared__ float sh[256];
        int j = b;
        float acc = 0.f;
        if (hasAff) {
            const float* W = (j < 128) ? (Wgc + j) : (Wgat + j - 128);
            for (int k = t; k < K; k += 256) {
                float mu = bnsumP[k] / (float)NN;
                float var = bnsqP[k] / (float)NN - mu * mu;
                float sck = gamP[k] * rsqrtf(var + 1e-5f);
                float shk = betP[k] - mu * sck;
                acc += shk * W[(size_t)k * 128];
            }
        }
        sh[t] = acc;
        __syncthreads();
        for (int off = 128; off; off >>= 1) {
            if (t < off) sh[t] += sh[t + off];
            __syncthreads();
        }
        if (t == 0) cvec[j] = sh[0];
        return;
    }
    b -= 256;
    int idx = b * 256 + t;
    if (idx < NN * 4) { el[idx] = 0.f; er[idx] = 0.f; }
    if (idx < CC) { bnsumC[idx] = 0.f; bnsqC[idx] = 0.f; }
    if (initAll) {
        if (idx < NN) { iso[idx] = 0.f; idegi[idx] = 0; idegc[idx] = 0; att[idx] = 0.f; }
        if (idx < GN * CC) gsum[idx] = 0.f;
        if (idx < GN) gcnt[idx] = 0.f;
    }
}

// ===================================================================
// Persistent dual-GEMM, fp16 m16n8k16 mma, cp.async 3-stage, BK=16
// ===================================================================
__global__ __launch_bounds__(512, 1) void gemm_dual_async(
    const float* __restrict__ A, const __half* __restrict__ Wp,
    const float* __restrict__ cvec,
    __half* __restrict__ Ca, __half* __restrict__ Cb,
    const float* __restrict__ rowscale,
    const float* __restrict__ alv, const float* __restrict__ arv,
    float* __restrict__ el, float* __restrict__ er,
    int M, int K, int H, int ntiles)
{
    __shared__ __align__(16) float As[3][128 * 16];
    __shared__ __align__(16) __half Bs[3][256 * 16];

    const int tid = threadIdx.x;
    const int lane = tid & 31;
    const int wid = tid >> 5;
    const int wm = wid & 3;
    const int wn = wid >> 2;
    const int iters = K >> 4;

    const int ar_ = tid >> 2, akg = tid & 3;
    const int a_soff = ar_ * 16 + ((akg * 4) ^ (4 * (ar_ & 3)));
    const int bn = tid >> 1, bg = tid & 1;
    const int b_soff = bn * 16 + ((bg ^ (bn & 1)) << 3);
    const __half* b_src_base = Wp + (size_t)bn * K + bg * 8;

    for (int tile = blockIdx.x; tile < ntiles; tile += gridDim.x) {
        const int row0 = tile * 128;
        const int a_sz = (row0 + ar_ < M) ? 16 : 0;
        const float* a_src_base = A + (size_t)(row0 + ar_) * K + akg * 4;

        float acc[2][8][4];
#pragma unroll
        for (int i = 0; i < 2; i++)
#pragma unroll
            for (int j = 0; j < 8; j++)
#pragma unroll
                for (int q = 0; q < 4; q++) acc[i][j][q] = 0.f;

        // drain any in-flight groups from previous tile before reusing smem
        asm volatile("cp.async.wait_group 0;" ::: "memory");
        __syncthreads();

        auto loadTile = [&](int it) {
            int buf = it % 3;
            int k0 = it * 16;
            cp16((uint32_t)__cvta_generic_to_shared(&As[buf][a_soff]), a_src_base + k0, a_sz);
            cp16((uint32_t)__cvta_generic_to_shared(&Bs[buf][b_soff]), b_src_base + k0, 16);
            asm volatile("cp.async.commit_group;" ::: "memory");
        };

        loadTile(0);
        if (iters > 1) loadTile(1);
        else asm volatile("cp.async.commit_group;" ::: "memory");

        for (int it = 0; it < iters; ++it) {
            asm volatile("cp.async.wait_group 1;" ::: "memory");
            __syncthreads();
            if (it + 2 < iters) loadTile(it + 2);
            else asm volatile("cp.async.commit_group;" ::: "memory");

            const float* as = As[it % 3];
            const __half* bs = Bs[it % 3];

            uint32_t afr[2][4], bfr[8][2];
            const int c = (lane & 3) * 2;
#pragma unroll
            for (int i = 0; i < 2; i++) {
                int r = wm * 32 + i * 16 + (lane >> 2);
                int r2 = r + 8;
                int sw = 4 * (r & 3);
                int sw2 = 4 * (r2 & 3);
                float2 f00 = *(const float2*)&as[r * 16 + (c ^ sw)];
                float2 f10 = *(const float2*)&as[r2 * 16 + (c ^ sw2)];
                float2 f01 = *(const float2*)&as[r * 16 + ((c + 8) ^ sw)];
                float2 f11 = *(const float2*)&as[r2 * 16 + ((c + 8) ^ sw2)];
                afr[i][0] = packh2(f00.x, f00.y);
                afr[i][1] = packh2(f10.x, f10.y);
                afr[i][2] = packh2(f01.x, f01.y);
                afr[i][3] = packh2(f11.x, f11.y);
            }
#pragma unroll
            for (int j = 0; j < 8; j++) {
                int n = wn * 64 + j * 8 + (lane >> 2);
                const __half* brow = bs + n * 16;
                int g0 = (0 ^ (n & 1)) << 3;
                int g1 = (1 ^ (n & 1)) << 3;
                bfr[j][0] = *(const uint32_t*)&brow[g0 + c];
                bfr[j][1] = *(const uint32_t*)&brow[g1 + c];
            }
#pragma unroll
            for (int i = 0; i < 2; i++)
#pragma unroll
                for (int j = 0; j < 8; j++)
                    mma_f16(acc[i][j], afr[i], bfr[j]);
        }

        // ---- store epilogue (fp16 outputs) ----
#pragma unroll
        for (int i = 0; i < 2; i++) {
            int r = row0 + wm * 32 + i * 16 + (lane >> 2);
#pragma unroll
            for (int j = 0; j < 8; j++) {
                int col = wn * 64 + j * 8 + (lane & 3) * 2;
                float c0 = __ldg(cvec + col), c1 = __ldg(cvec + col + 1);
                __half* dstm;
                int cc;
                bool isA = (col < 128);
                if (isA) { dstm = Ca; cc = col; }
                else     { dstm = Cb; cc = col - 128; }
                if (r < M) {
                    float s = isA ? __ldg(rowscale + r) : 1.f;
                    *(__half2*)(dstm + (size_t)r * 128 + cc) =
                        __floats2half2_rn((acc[i][j][0] + c0) * s, (acc[i][j][1] + c1) * s);
                }
                if (r + 8 < M) {
                    float s = isA ? __ldg(rowscale + r + 8) : 1.f;
                    *(__half2*)(dstm + (size_t)(r + 8) * 128 + cc) =
                        __floats2half2_rn((acc[i][j][2] + c0) * s, (acc[i][j][3] + c1) * s);
                }
            }
        }

        // ---- fused el/er from fp32 accumulators (wn >= 2) ----
        if (wn >= 2) {
            const int hmask = (H == 4) ? 1 : 0;
            float pel[4][2], per_[4][2];
#pragma unroll
            for (int rr = 0; rr < 4; rr++) { pel[rr][0] = pel[rr][1] = 0.f; per_[rr][0] = per_[rr][1] = 0.f; }
#pragma unroll
            for (int i = 0; i < 2; i++)
#pragma unroll
                for (int j = 0; j < 8; j++) {
                    int col = wn * 64 + j * 8 + (lane & 3) * 2;
                    int cf = col - 128;
                    float a0 = __ldg(alv + cf), a1 = __ldg(alv + cf + 1);
                    float b0 = __ldg(arv + cf), b1 = __ldg(arv + cf + 1);
                    float c0 = __ldg(cvec + col), c1 = __ldg(cvec + col + 1);
                    int hg = (j >> 2) & hmask;
                    float f0 = acc[i][j][0] + c0, f1 = acc[i][j][1] + c1;
                    float f2 = acc[i][j][2] + c0, f3 = acc[i][j][3] + c1;
                    pel[i * 2 + 0][hg] += f0 * a0 + f1 * a1;
                    per_[i * 2 + 0][hg] += f0 * b0 + f1 * b1;
                    pel[i * 2 + 1][hg] += f2 * a0 + f3 * a1;
                    per_[i * 2 + 1][hg] += f2 * b0 + f3 * b1;
                }
#pragma unroll
            for (int rr = 0; rr < 4; rr++)
#pragma unroll
                for (int hg = 0; hg < 2; hg++) {
                    float v = pel[rr][hg];
                    v += __shfl_xor_sync(0xffffffffu, v, 1);
                    v += __shfl_xor_sync(0xffffffffu, v, 2);
                    pel[rr][hg] = v;
                    float w = per_[rr][hg];
                    w += __shfl_xor_sync(0xffffffffu, w, 1);
                    w += __shfl_xor_sync(0xffffffffu, w, 2);
                    per_[rr][hg] = w;
                }
            if ((lane & 3) == 0) {
#pragma unroll
                for (int rr = 0; rr < 4; rr++) {
                    int row = row0 + wm * 32 + (rr >> 1) * 16 + (lane >> 2) + (rr & 1) * 8;
                    if (row < M) {
#pragma unroll
                        for (int hg = 0; hg < 2; hg++) {
                            if (hg > hmask) break;
                            int h = (H == 4) ? ((wn - 2) * 2 + hg) : 0;
                            atomicAdd(&el[(size_t)row * H + h], pel[rr][hg]);
                            atomicAdd(&er[(size_t)row * H + h], per_[rr][hg]);
                        }
                    }
                }
            }
        }
    }
}

// ===================================================================
// Fused layer: per-warp softmax prologue + FROZEN gather structure
// ===================================================================
template<int H, int DO_LEAKY, int DO_ATT>
__global__ __launch_bounds__(128) void layer_fused(
    const __half* __restrict__ xw, const __half* __restrict__ f,
    const float* __restrict__ el, const float* __restrict__ er,
    const float* __restrict__ isi,
    const int* __restrict__ rpi, const int* __restrict__ degi, const int* __restrict__ ci,
    const int* __restrict__ rpc, const int* __restrict__ degc, const int* __restrict__ ccol,
    const float* __restrict__ bgc, const float* __restrict__ bga,
    float* __restrict__ z, float* __restrict__ bnsum, float* __restrict__ bnsq,
    float* __restrict__ att)
{
    const int ch = threadIdx.x;
    const int lane = ch & 31;
    const int wid = ch >> 5;
    const int hh = (H == 1) ? 0 : wid;
    const float bc = __ldg(bgc + ch) + __ldg(bga + ch);
    float ls = 0.f, lq = 0.f;

    for (int n = blockIdx.x; n < NN; n += gridDim.x) {
        float a = 0.f;
        int j = __ldg(rpi + n);
        int bend = j + __ldg(degi + n);
        for (; j + 4 <= bend; j += 4) {
            int s0 = __ldg(ci + j), s1 = __ldg(ci + j + 1);
            int s2 = __ldg(ci + j + 2), s3 = __ldg(ci + j + 3);
            float v0 = __half2float(__ldg(xw + (size_t)s0 * 128 + ch));
            float v1 = __half2float(__ldg(xw + (size_t)s1 * 128 + ch));
            float v2 = __half2float(__ldg(xw + (size_t)s2 * 128 + ch));
            float v3 = __half2float(__ldg(xw + (size_t)s3 * 128 + ch));
            a += (v0 + v1) + (v2 + v3);
        }
        for (; j < bend; j++)
            a += __half2float(__ldg(xw + (size_t)__ldg(ci + j) * 128 + ch));

        float g = 0.f;
        int c0 = __ldg(rpc + n), deg = __ldg(degc + n);
        if (deg > 0) {
            float ern = __ldg(er + (size_t)n * H + hh);
            if (deg <= 32) {
                int sn = 0;
                float e = -1e30f;
                bool valid = (lane < deg);
                if (valid) {
                    sn = __ldg(ccol + c0 + lane);
                    e = leakyr(__ldg(el + (size_t)sn * H + hh) + ern);
                }
                float m = e;
#pragma unroll
                for (int off = 16; off; off >>= 1)
                    m = fmaxf(m, __shfl_xor_sync(0xffffffffu, m, off));
                float ex = valid ? __expf(e - m) : 0.f;
                float s = ex;
#pragma unroll
                for (int off = 16; off; off >>= 1)
                    s += __shfl_xor_sync(0xffffffffu, s, off);
                float aj = ex / s;
                if (DO_ATT && wid == 0 && valid) atomicAdd(&att[sn], aj);
                int kk = 0;
                for (; kk + 4 <= deg; kk += 4) {
                    int s0 = __shfl_sync(0xffffffffu, sn, kk);
                    int s1 = __shfl_sync(0xffffffffu, sn, kk + 1);
                    int s2 = __shfl_sync(0xffffffffu, sn, kk + 2);
                    int s3 = __shfl_sync(0xffffffffu, sn, kk + 3);
                    float a0 = __shfl_sync(0xffffffffu, aj, kk);
                    float a1 = __shfl_sync(0xffffffffu, aj, kk + 1);
                    float a2 = __shfl_sync(0xffffffffu, aj, kk + 2);
                    float a3 = __shfl_sync(0xffffffffu, aj, kk + 3);
                    float v0 = __half2float(__ldg(f + (size_t)s0 * 128 + ch));
                    float v1 = __half2float(__ldg(f + (size_t)s1 * 128 + ch));
                    float v2 = __half2float(__ldg(f + (size_t)s2 * 128 + ch));
                    float v3 = __half2float(__ldg(f + (size_t)s3 * 128 + ch));
                    g += a0 * v0 + a1 * v1 + a2 * v2 + a3 * v3;
                }
                for (; kk < deg; kk++) {
                    int s0 = __shfl_sync(0xffffffffu, sn, kk);
                    float a0 = __shfl_sync(0xffffffffu, aj, kk);
                    g += a0 * __half2float(__ldg(f + (size_t)s0 * 128 + ch));
                }
            } else {
                int cend = c0 + deg;
                float m = -1e30f, s = 0.f;
                for (int jj = c0 + lane; jj < cend; jj += 32) {
                    int sn = __ldg(ccol + jj);
                    float e = leakyr(__ldg(el + (size_t)sn * H + hh) + ern);
                    if (e > m) { s *= __expf(m - e); m = e; }
                    s += __expf(e - m);
                }
#pragma unroll
                for (int off = 16; off; off >>= 1) {
                    float mo = __shfl_xor_sync(0xffffffffu, m, off);
                    float so = __shfl_xor_sync(0xffffffffu, s, off);
                    float mm = fmaxf(m, mo);
                    s = s * __expf(m - mm) + so * __expf(mo - mm);
                    m = mm;
                }
                float inv = 1.f / s;
                for (int j0 = c0; j0 < cend; j0 += 32) {
                    int cnt = min(32, cend - j0);
                    int sn = 0;
                    float aj = 0.f;
                    if (lane < cnt) {
                        sn = __ldg(ccol + j0 + lane);
                        float e = leakyr(__ldg(el + (size_t)sn * H + hh) + ern);
                        aj = __expf(e - m) * inv;
                        if (DO_ATT && wid == 0) atomicAdd(&att[sn], aj);
                    }
                    for (int kk = 0; kk < cnt; kk++) {
                        int s0 = __shfl_sync(0xffffffffu, sn, kk);
                        float a0 = __shfl_sync(0xffffffffu, aj, kk);
                        g += a0 * __half2float(__ldg(f + (size_t)s0 * 128 + ch));
                    }
                }
            }
        }

        float v = a * __ldg(isi + n) + g + bc;
        if (DO_LEAKY) v = leakyr(v);
        z[(size_t)n * 128 + ch] = v;
        ls += v;
        lq += v * v;
    }
    atomicAdd(&bnsum[ch], ls);
    atomicAdd(&bnsq[ch], lq);
}

// -------- pooling: sorted-gid segment accumulation + inline BN --------
__global__ __launch_bounds__(128) void pool_sorted(
    const float* __restrict__ z,
    const float* __restrict__ bnsum, const float* __restrict__ bnsq,
    const float* __restrict__ gam, const float* __restrict__ bet,
    const float* __restrict__ att,
    const int* __restrict__ gid, float* gsum)
{
    const int ch = threadIdx.x;
    int n0 = blockIdx.x * 64;
    int n1 = min(n0 + 64, NN);
    if (n0 >= NN) return;
    float mu = __ldg(bnsum + ch) / (float)NN;
    float var = __ldg(bnsq + ch) / (float)NN - mu * mu;
    float sc = __ldg(gam + ch) * rsqrtf(var + 1e-5f);
    float sh = __ldg(bet + ch) - mu * sc;

    int cur = __ldg(gid + n0);
    float acc = 0.f;
    for (int n = n0; n < n1; n++) {
        int gg = __ldg(gid + n);
        if (gg != cur) {
            atomicAdd(&gsum[cur * 128 + ch], acc);
            acc = 0.f;
            cur = gg;
        }
        float v = z[(size_t)n * 128 + ch] * sc + sh;
        acc += v * __ldg(att + n);
    }
    atomicAdd(&gsum[cur * 128 + ch], acc);
}
__global__ void out_kernel(const float* __restrict__ gsum, const float* __restrict__ gcnt,
                           const float* __restrict__ att, float* __restrict__ out)
{
    int i = blockIdx.x * blockDim.x + threadIdx.x;
    if (i < GN * 128) {
        out[i] = gsum[i] / fmaxf(gcnt[i >> 7], 1.f);
    } else if (i < GN * 128 + NN) {
        out[i] = att[i - GN * 128];
    }
}

static inline int cdiv(int a, int b) { return (a + b - 1) / b; }

extern "C" void kernel_launch(void* const* d_in, const int* in_sizes, int n_in,
                              void* d_out, int out_size)
{
    (void)in_sizes; (void)n_in; (void)out_size;
    const float* feat = (const float*)d_in[0];
    const int* isrc = (const int*)d_in[1];
    const int* idst = (const int*)d_in[2];
    const int* csrc = (const int*)d_in[3];
    const int* cdst = (const int*)d_in[4];
    const int* gid  = (const int*)d_in[5];
    const float* Wgc[3]  = {(const float*)d_in[6],  (const float*)d_in[12], (const float*)d_in[18]};
    const float* bgc[3]  = {(const float*)d_in[7],  (const float*)d_in[13], (const float*)d_in[19]};
    const float* Wgat[3] = {(const float*)d_in[8],  (const float*)d_in[14], (const float*)d_in[20]};
    const float* al[3]   = {(const float*)d_in[9],  (const float*)d_in[15], (const float*)d_in[21]};
    const float* ar[3]   = {(const float*)d_in[10], (const float*)d_in[16], (const float*)d_in[22]};
    const float* bga[3]  = {(const float*)d_in[11], (const float*)d_in[17], (const float*)d_in[23]};
    const float* gam[3]  = {(const float*)d_in[24], (const float*)d_in[26], (const float*)d_in[28]};
    const float* bet[3]  = {(const float*)d_in[25], (const float*)d_in[27], (const float*)d_in[29]};
    float* out = (float*)d_out;

    __half *xw, *f, *wp;
    float *z, *el, *er, *cvec;
    float *iso, *isi, *att, *gsum, *gcnt, *bnsum, *bnsq;
    int *idegi, *idegc, *rpi, *rpc, *curi, *curc, *bsum, *ci, *ccol;
    cudaGetSymbolAddress((void**)&xw, g_xw);
    cudaGetSymbolAddress((void**)&f, g_f);
    cudaGetSymbolAddress((void**)&z, g_z);
    cudaGetSymbolAddress((void**)&el, g_el);
    cudaGetSymbolAddress((void**)&er, g_er);
    cudaGetSymbolAddress((void**)&wp, g_wp);
    cudaGetSymbolAddress((void**)&cvec, g_cvec);
    cudaGetSymbolAddress((void**)&iso, g_iso);
    cudaGetSymbolAddress((void**)&isi, g_isi);
    cudaGetSymbolAddress((void**)&att, g_att);
    cudaGetSymbolAddress((void**)&gsum, g_gsum);
    cudaGetSymbolAddress((void**)&gcnt, g_gcnt);
    cudaGetSymbolAddress((void**)&bnsum, g_bnsum);
    cudaGetSymbolAddress((void**)&bnsq, g_bnsq);
    cudaGetSymbolAddress((void**)&idegi, g_idegi);
    cudaGetSymbolAddress((void**)&idegc, g_idegc);
    cudaGetSymbolAddress((void**)&rpi, g_rpi);
    cudaGetSymbolAddress((void**)&rpc, g_rpc);
    cudaGetSymbolAddress((void**)&curi, g_curi);
    cudaGetSymbolAddress((void**)&curc, g_curc);
    cudaGetSymbolAddress((void**)&bsum, g_bsum);
    cudaGetSymbolAddress((void**)&ci, g_ci);
    cudaGetSymbolAddress((void**)&ccol, g_ccol);

    int nsm = 148;
    cudaDeviceGetAttribute(&nsm, cudaDevAttrMultiProcessorCount, 0);
    if (nsm < 1) nsm = 148;
    const int NB = cdiv(NN, 256);
    const int ZB = cdiv(NN * 4, 256);
    const int NT = cdiv(NN, 128);   // GEMM tiles

    // layer-0 prep + ALL one-time zeroing
    prep_all<<<FDIM + 256 + ZB, 256>>>(Wgc[0], Wgat[0], nullptr, nullptr,
                                       nullptr, nullptr, 0, FDIM, wp, cvec,
                                       el, er, bnsum, bnsq,
                                       1, iso, idegi, idegc, att, gsum, gcnt);
    edge_deg<<<cdiv(EIN + ECN + NN, 256), 256>>>(isrc, idst, cdst, gid, iso, idegi, idegc, gcnt);
    scan1dual<<<NB, 256>>>(idegi, idegc, rpi, rpc, bsum, iso, isi, NN);
    scan2dual<<<1, 512>>>(bsum, NB);
    scan3dual<<<NB, 256>>>(rpi, rpc, bsum, curi, curc, NN);
    scatter_dual<<<cdiv(EIN + ECN, 256), 256>>>(isrc, idst, csrc, cdst, curi, curc, ci, ccol);

    const int Hs[3] = {4, 4, 1};
    for (int L = 0; L < 3; L++) {
        int K = (L == 0) ? FDIM : CC;
        int H = Hs[L];
        int cur = (L & 1) * CC;
        int prev = ((L + 1) & 1) * CC;

        if (L > 0)
            prep_all<<<K + 256 + ZB, 256>>>(Wgc[L], Wgat[L], gam[L - 1], bet[L - 1],
                                            bnsum + prev, bnsq + prev, 1, K, wp, cvec,
                                            el, er, bnsum + cur, bnsq + cur,
                                            0, nullptr, nullptr, nullptr, nullptr,
                                            nullptr, nullptr);

        gemm_dual_async<<<nsm, 512>>>((L == 0) ? feat : z, wp, cvec, xw, f,
                                      iso, al[L], ar[L], el, er, NN, K, H, NT);

        if (L < 2)
            layer_fused<4, 1, 0><<<2048, 128>>>(xw, f, el, er, isi, rpi, idegi, ci,
                                                rpc, idegc, ccol, bgc[L], bga[L],
                                                z, bnsum + cur, bnsq + cur, att);
        else
            layer_fused<1, 0, 1><<<2048, 128>>>(xw, f, el, er, isi, rpi, idegi, ci,
                                                rpc, idegc, ccol, bgc[L], bga[L],
                                                z, bnsum + cur, bnsq + cur, att);
    }

    // ---- pooling: layer-2 parity = set 0 ----
    pool_sorted<<<cdiv(NN, 64), 128>>>(z, bnsum, bnsq, gam[2], bet[2], att, gid, gsum);
    out_kernel<<<cdiv(GN * CC + NN, 256), 256>>>(gsum, gcnt, att, out);
}